// round 1
// baseline (speedup 1.0000x reference)
#include <cuda_runtime.h>

#define NN 50000
#define NE 800000
#define NG 64
#define H  128
#define CL 16
#define ODIM 128

// ---------------- scratch (device globals; no allocation allowed) ----------------
__device__ float g_x[NN * H];
__device__ float g_m[NN * H];
__device__ float g_y[NN * H];
__device__ int   g_deg[NN];
__device__ int   g_off[NN + 1];
__device__ int   g_cur[NN];
__device__ int   g_csr[NE];
__device__ float g_scores[NN * CL];
__device__ int   g_goff[NG + 1];
__device__ float g_stats[2 * H];
__device__ float g_scale[H];
__device__ float g_shift[H];
__device__ float g_clust[NG * CL * H];

// ---------------- CSR build ----------------
__global__ void k_deg(const int* __restrict__ dst, int e) {
    int i = blockIdx.x * blockDim.x + threadIdx.x;
    if (i < e) atomicAdd(&g_deg[dst[i]], 1);
}

// single block, 1024 threads: exclusive scan of g_deg -> g_off, copy to g_cur
__global__ void k_scan(int n) {
    __shared__ int wsum[32];
    __shared__ int carry;
    int t = threadIdx.x;
    if (t == 0) carry = 0;
    __syncthreads();
    for (int base = 0; base < n; base += 1024) {
        int i = base + t;
        int v = (i < n) ? g_deg[i] : 0;
        int x = v;
        #pragma unroll
        for (int d = 1; d < 32; d <<= 1) {
            int y = __shfl_up_sync(0xffffffffu, x, d);
            if ((t & 31) >= d) x += y;
        }
        if ((t & 31) == 31) wsum[t >> 5] = x;
        __syncthreads();
        if (t < 32) {
            int z = wsum[t];
            #pragma unroll
            for (int d = 1; d < 32; d <<= 1) {
                int y = __shfl_up_sync(0xffffffffu, z, d);
                if (t >= d) z += y;
            }
            wsum[t] = z;   // inclusive warp-sum scan
        }
        __syncthreads();
        int incl = x + ((t >= 32) ? wsum[(t >> 5) - 1] : 0);
        int excl = incl - v + carry;
        if (i < n) { g_off[i] = excl; g_cur[i] = excl; }
        __syncthreads();
        if (t == 1023) carry += incl;  // incl at t=1023 == block total
        __syncthreads();
    }
    if (t == 0) g_off[n] = carry;
}

__global__ void k_scatter(const int* __restrict__ src, const int* __restrict__ dst, int e) {
    int i = blockIdx.x * blockDim.x + threadIdx.x;
    if (i < e) {
        int d = dst[i];
        int p = atomicAdd(&g_cur[d], 1);
        g_csr[p] = src[i];
    }
}

// ---------------- embedding gather ----------------
__global__ void k_embed(const float* __restrict__ emb, const int* __restrict__ degidx, int n) {
    int i = blockIdx.x * blockDim.x + threadIdx.x;  // over n*32 float4s
    if (i < n * 32) {
        int node = i >> 5, q = i & 31;
        int d = degidx[node];
        ((float4*)g_x)[i] = ((const float4*)(emb + (size_t)d * H))[q];
    }
}

// graph segment offsets from sorted batch
__global__ void k_goff(const int* __restrict__ batch, int n) {
    int i = blockIdx.x * blockDim.x + threadIdx.x;
    if (i < n) {
        int b  = batch[i];
        int bp = (i == 0) ? -1 : batch[i - 1];
        for (int g = bp + 1; g <= b; g++) g_goff[g] = i;
        if (i == n - 1) {
            for (int g = b + 1; g <= NG; g++) g_goff[g] = n;
        }
    }
}

// ---------------- mean aggregation: one warp per node ----------------
__global__ void __launch_bounds__(256) k_agg(int n) {
    int w    = (blockIdx.x * blockDim.x + threadIdx.x) >> 5;
    int lane = threadIdx.x & 31;
    if (w >= n) return;
    int beg = g_off[w], end = g_off[w + 1];
    float4 acc = make_float4(0.f, 0.f, 0.f, 0.f);
    for (int e = beg; e < end; e++) {
        int s = g_csr[e];
        float4 v = *(const float4*)&g_x[(size_t)s * H + lane * 4];
        acc.x += v.x; acc.y += v.y; acc.z += v.z; acc.w += v.w;
    }
    int cnt = end - beg;
    float inv = 1.f / (float)(cnt > 1 ? cnt : 1);
    acc.x *= inv; acc.y *= inv; acc.z *= inv; acc.w *= inv;
    *(float4*)&g_m[(size_t)w * H + lane * 4] = acc;
}

// ---------------- fused dual GEMM + bias + batchnorm partial stats ----------------
// Y = M @ Wl + X @ Wr + bl ; accumulate per-column sum/sumsq into g_stats
#define GEMM_SMEM ((256 * 128 + 16 * 132 + 256) * 4)
__global__ void __launch_bounds__(256) k_gemm(const float* __restrict__ Wl,
                                              const float* __restrict__ Wr,
                                              const float* __restrict__ bl, int n) {
    extern __shared__ float sm[];
    float* Ws   = sm;                       // [256][128]  (Wl rows 0..127, Wr rows 128..255)
    float* As   = sm + 256 * 128;           // [16][132]   transposed A tile
    float* sred = As + 16 * 132;            // [256]       col sums / sumsq

    int t = threadIdx.x;
    for (int i = t; i < 128 * 128; i += 256) {
        Ws[i]             = Wl[i];
        Ws[128 * 128 + i] = Wr[i];
    }
    sred[t] = 0.f;

    int rowBase = blockIdx.x * 128;
    int ty = t >> 4, tx = t & 15;
    float acc[8][8];
    #pragma unroll
    for (int i = 0; i < 8; i++)
        #pragma unroll
        for (int j = 0; j < 8; j++) acc[i][j] = 0.f;

    int r = t >> 1, kh = (t & 1) * 8;

    for (int k0 = 0; k0 < 256; k0 += 16) {
        __syncthreads();
        const float* A = (k0 < 128) ? g_m : g_x;
        int grow = rowBase + r;
        float4 v0 = make_float4(0.f, 0.f, 0.f, 0.f);
        float4 v1 = make_float4(0.f, 0.f, 0.f, 0.f);
        if (grow < n) {
            const float4* p = (const float4*)&A[(size_t)grow * H + (k0 & 127) + kh];
            v0 = p[0]; v1 = p[1];
        }
        As[(kh + 0) * 132 + r] = v0.x; As[(kh + 1) * 132 + r] = v0.y;
        As[(kh + 2) * 132 + r] = v0.z; As[(kh + 3) * 132 + r] = v0.w;
        As[(kh + 4) * 132 + r] = v1.x; As[(kh + 5) * 132 + r] = v1.y;
        As[(kh + 6) * 132 + r] = v1.z; As[(kh + 7) * 132 + r] = v1.w;
        __syncthreads();

        #pragma unroll
        for (int kk = 0; kk < 16; kk++) {
            float4 a0 = *(const float4*)&As[kk * 132 + ty * 8];
            float4 a1 = *(const float4*)&As[kk * 132 + ty * 8 + 4];
            const float* wr = &Ws[(k0 + kk) * 128 + tx * 8];
            float4 w0 = *(const float4*)wr;
            float4 w1 = *(const float4*)(wr + 4);
            float a[8] = {a0.x, a0.y, a0.z, a0.w, a1.x, a1.y, a1.z, a1.w};
            float w[8] = {w0.x, w0.y, w0.z, w0.w, w1.x, w1.y, w1.z, w1.w};
            #pragma unroll
            for (int i = 0; i < 8; i++)
                #pragma unroll
                for (int j = 0; j < 8; j++) acc[i][j] += a[i] * w[j];
        }
    }
    __syncthreads();

    float b[8];
    #pragma unroll
    for (int j = 0; j < 8; j++) b[j] = bl[tx * 8 + j];

    float cs[8], cq[8];
    #pragma unroll
    for (int j = 0; j < 8; j++) { cs[j] = 0.f; cq[j] = 0.f; }

    #pragma unroll
    for (int i = 0; i < 8; i++) {
        int grow = rowBase + ty * 8 + i;
        if (grow < n) {
            float y[8];
            #pragma unroll
            for (int j = 0; j < 8; j++) {
                y[j] = acc[i][j] + b[j];
                cs[j] += y[j];
                cq[j] += y[j] * y[j];
            }
            float* dstp = &g_y[(size_t)grow * H + tx * 8];
            float4 o0 = {y[0], y[1], y[2], y[3]};
            float4 o1 = {y[4], y[5], y[6], y[7]};
            *(float4*)dstp       = o0;
            *(float4*)(dstp + 4) = o1;
        }
    }
    #pragma unroll
    for (int j = 0; j < 8; j++) {
        atomicAdd(&sred[tx * 8 + j],       cs[j]);
        atomicAdd(&sred[128 + tx * 8 + j], cq[j]);
    }
    __syncthreads();
    if (t < 128) {
        atomicAdd(&g_stats[t],       sred[t]);
        atomicAdd(&g_stats[128 + t], sred[128 + t]);
    }
}

__global__ void k_statfinal(const float* __restrict__ gamma, const float* __restrict__ beta, int n) {
    int c = threadIdx.x;  // 128
    float s = g_stats[c], s2 = g_stats[128 + c];
    float invn = 1.f / (float)n;
    float mu  = s * invn;
    float var = s2 * invn - mu * mu;
    float rs  = rsqrtf(var + 1e-5f);
    float sc  = rs * gamma[c];
    g_scale[c] = sc;
    g_shift[c] = beta[c] - mu * sc;
    g_stats[c] = 0.f;          // reset for next layer / next replay
    g_stats[128 + c] = 0.f;
}

__global__ void k_norm(int n) {
    int i = blockIdx.x * blockDim.x + threadIdx.x;  // over n*32 float4s
    if (i < n * 32) {
        int q = i & 31;
        float4 y  = ((const float4*)g_y)[i];
        float4 sc = *(const float4*)&g_scale[q * 4];
        float4 sh = *(const float4*)&g_shift[q * 4];
        float4 r;
        r.x = fmaxf(y.x * sc.x + sh.x, 0.f);
        r.y = fmaxf(y.y * sc.y + sh.y, 0.f);
        r.z = fmaxf(y.z * sc.z + sh.z, 0.f);
        r.w = fmaxf(y.w * sc.w + sh.w, 0.f);
        ((float4*)g_x)[i] = r;
    }
}

// ---------------- attention scores: 32 nodes / block staged in smem ----------------
__global__ void __launch_bounds__(128) k_scores(const float* __restrict__ attn_W,
                                                const float* __restrict__ attn_b, int n) {
    __shared__ float Xs[32 * 132];
    __shared__ float Ws[128 * CL];
    __shared__ float bs[CL];
    int t = threadIdx.x;
    for (int i = t; i < 128 * CL; i += 128) Ws[i] = attn_W[i];
    if (t < CL) bs[t] = attn_b[t];
    int nb = blockIdx.x * 32;
    for (int i = t; i < 1024; i += 128) {   // 32 rows * 32 float4
        int row = i >> 5, q = i & 31;
        float4 v = make_float4(0.f, 0.f, 0.f, 0.f);
        int node = nb + row;
        if (node < n) v = *(const float4*)&g_x[(size_t)node * H + q * 4];
        *(float4*)&Xs[row * 132 + q * 4] = v;
    }
    __syncthreads();
    int c = t & 15, ng = t >> 4;            // 8 groups of 4 nodes x 16 clusters
    float a0 = bs[c], a1 = bs[c], a2 = bs[c], a3 = bs[c];
    const float* x0 = &Xs[(ng * 4 + 0) * 132];
    const float* x1 = &Xs[(ng * 4 + 1) * 132];
    const float* x2 = &Xs[(ng * 4 + 2) * 132];
    const float* x3 = &Xs[(ng * 4 + 3) * 132];
    #pragma unroll
    for (int k = 0; k < 128; k += 4) {
        float w0 = Ws[(k + 0) * CL + c], w1 = Ws[(k + 1) * CL + c];
        float w2 = Ws[(k + 2) * CL + c], w3 = Ws[(k + 3) * CL + c];
        float4 v;
        v = *(const float4*)&x0[k]; a0 += v.x * w0 + v.y * w1 + v.z * w2 + v.w * w3;
        v = *(const float4*)&x1[k]; a1 += v.x * w0 + v.y * w1 + v.z * w2 + v.w * w3;
        v = *(const float4*)&x2[k]; a2 += v.x * w0 + v.y * w1 + v.z * w2 + v.w * w3;
        v = *(const float4*)&x3[k]; a3 += v.x * w0 + v.y * w1 + v.z * w2 + v.w * w3;
    }
    int node = nb + ng * 4;
    if (node + 0 < n) g_scores[(size_t)(node + 0) * CL + c] = a0;
    if (node + 1 < n) g_scores[(size_t)(node + 1) * CL + c] = a1;
    if (node + 2 < n) g_scores[(size_t)(node + 2) * CL + c] = a2;
    if (node + 3 < n) g_scores[(size_t)(node + 3) * CL + c] = a3;
}

// ---------------- per-graph softmax pooling: one block per graph ----------------
__global__ void __launch_bounds__(256) k_pool() {
    int g = blockIdx.x, t = threadIdx.x, lane = t & 31, wid = t >> 5;
    int beg = g_goff[g], end = g_goff[g + 1];
    __shared__ float red[CL][9];
    __shared__ float smax[CL], sinv[CL];
    float lv[CL];
    #pragma unroll
    for (int c = 0; c < CL; c++) lv[c] = -1e30f;
    for (int i = beg + t; i < end; i += 256) {
        const float4* sp = (const float4*)&g_scores[(size_t)i * CL];
        #pragma unroll
        for (int q = 0; q < 4; q++) {
            float4 s = sp[q];
            lv[4 * q + 0] = fmaxf(lv[4 * q + 0], s.x);
            lv[4 * q + 1] = fmaxf(lv[4 * q + 1], s.y);
            lv[4 * q + 2] = fmaxf(lv[4 * q + 2], s.z);
            lv[4 * q + 3] = fmaxf(lv[4 * q + 3], s.w);
        }
    }
    #pragma unroll
    for (int c = 0; c < CL; c++) {
        float v = lv[c];
        #pragma unroll
        for (int o = 16; o; o >>= 1) v = fmaxf(v, __shfl_xor_sync(0xffffffffu, v, o));
        if (lane == 0) red[c][wid] = v;
    }
    __syncthreads();
    if (t < CL) {
        float v = red[t][0];
        #pragma unroll
        for (int w = 1; w < 8; w++) v = fmaxf(v, red[t][w]);
        smax[t] = v;
    }
    __syncthreads();
    #pragma unroll
    for (int c = 0; c < CL; c++) lv[c] = 0.f;
    for (int i = beg + t; i < end; i += 256) {
        const float4* sp = (const float4*)&g_scores[(size_t)i * CL];
        #pragma unroll
        for (int q = 0; q < 4; q++) {
            float4 s = sp[q];
            lv[4 * q + 0] += expf(s.x - smax[4 * q + 0]);
            lv[4 * q + 1] += expf(s.y - smax[4 * q + 1]);
            lv[4 * q + 2] += expf(s.z - smax[4 * q + 2]);
            lv[4 * q + 3] += expf(s.w - smax[4 * q + 3]);
        }
    }
    #pragma unroll
    for (int c = 0; c < CL; c++) {
        float v = lv[c];
        #pragma unroll
        for (int o = 16; o; o >>= 1) v += __shfl_xor_sync(0xffffffffu, v, o);
        if (lane == 0) red[c][wid] = v;
    }
    __syncthreads();
    if (t < CL) {
        float v = 0.f;
        #pragma unroll
        for (int w = 0; w < 8; w++) v += red[t][w];
        sinv[t] = 1.f / v;
    }
    __syncthreads();
    int c = t >> 4, h0 = (t & 15) * 8;
    float acc[8];
    #pragma unroll
    for (int j = 0; j < 8; j++) acc[j] = 0.f;
    float mx = smax[c], iv = sinv[c];
    for (int i = beg; i < end; i++) {
        float w = expf(g_scores[(size_t)i * CL + c] - mx) * iv;
        const float* xp = &g_x[(size_t)i * H + h0];
        float4 v0 = *(const float4*)xp;
        float4 v1 = *(const float4*)(xp + 4);
        acc[0] += w * v0.x; acc[1] += w * v0.y; acc[2] += w * v0.z; acc[3] += w * v0.w;
        acc[4] += w * v1.x; acc[5] += w * v1.y; acc[6] += w * v1.z; acc[7] += w * v1.w;
    }
    float* op = &g_clust[((size_t)g * CL + c) * H + h0];
    float4 o0 = {acc[0], acc[1], acc[2], acc[3]};
    float4 o1 = {acc[4], acc[5], acc[6], acc[7]};
    *(float4*)op       = o0;
    *(float4*)(op + 4) = o1;
}

// ---------------- final projection: clust[1024,128] @ out_W[128,128] ----------------
__global__ void __launch_bounds__(256) k_out(const float* __restrict__ W,
                                             const float* __restrict__ b,
                                             float* __restrict__ out) {
    int row  = blockIdx.x * 8 + (threadIdx.x >> 5);
    int lane = threadIdx.x & 31;
    if (row >= NG * CL) return;
    float4 acc = *(const float4*)&b[lane * 4];
    const float* cl = &g_clust[(size_t)row * H];
    #pragma unroll 4
    for (int k = 0; k < H; k++) {
        float c  = cl[k];
        float4 w = *(const float4*)&W[(size_t)k * ODIM + lane * 4];
        acc.x += c * w.x; acc.y += c * w.y; acc.z += c * w.z; acc.w += c * w.w;
    }
    *(float4*)&out[(size_t)row * ODIM + lane * 4] = acc;
}

// ---------------- launch ----------------
extern "C" void kernel_launch(void* const* d_in, const int* in_sizes, int n_in,
                              void* d_out, int out_size) {
    const float* emb    = (const float*)d_in[0];
    const float* Wl     = (const float*)d_in[1];
    const float* bl     = (const float*)d_in[2];
    const float* Wr     = (const float*)d_in[3];
    const float* gamma  = (const float*)d_in[4];
    const float* beta   = (const float*)d_in[5];
    const float* attn_W = (const float*)d_in[6];
    const float* attn_b = (const float*)d_in[7];
    const float* out_W  = (const float*)d_in[8];
    const float* out_b  = (const float*)d_in[9];
    const int* deg_idx  = (const int*)d_in[10];
    const int* edge     = (const int*)d_in[11];
    const int* batch    = (const int*)d_in[12];
    float* out          = (float*)d_out;

    const int n = NN, e = NE;

    cudaFuncSetAttribute(k_gemm, cudaFuncAttributeMaxDynamicSharedMemorySize, GEMM_SMEM);

    void* degp = nullptr;
    cudaGetSymbolAddress(&degp, g_deg);
    cudaMemsetAsync(degp, 0, NN * sizeof(int));

    k_deg<<<(e + 255) / 256, 256>>>(edge + e, e);
    k_scan<<<1, 1024>>>(n);
    k_scatter<<<(e + 255) / 256, 256>>>(edge, edge + e, e);
    k_embed<<<(n * 32 + 255) / 256, 256>>>(emb, deg_idx, n);
    k_goff<<<(n + 255) / 256, 256>>>(batch, n);

    for (int l = 0; l < 3; l++) {
        k_agg<<<(n * 32 + 255) / 256, 256>>>(n);
        k_gemm<<<(n + 127) / 128, 256, GEMM_SMEM>>>(Wl + l * H * H, Wr + l * H * H,
                                                    bl + l * H, n);
        k_statfinal<<<1, 128>>>(gamma + l * H, beta + l * H, n);
        k_norm<<<(n * 32 + 255) / 256, 256>>>(n);
    }

    k_scores<<<(n + 31) / 32, 128>>>(attn_W, attn_b, n);
    k_pool<<<NG, 256>>>();
    k_out<<<(NG * CL) / 8, 256>>>(out_W, out_b, out);
}

// round 2
// speedup vs baseline: 1.0917x; 1.0917x over previous
#include <cuda_runtime.h>
#include <cstdint>

#define NN 50000
#define NE 800000
#define NG 64
#define H  128
#define CL 16
#define ODIM 128

// ---------------- scratch (device globals; no allocation allowed) ----------------
__device__ float g_x[NN * H];
__device__ float g_m[NN * H];
__device__ float g_y[NN * H];
__device__ int   g_deg[NN];
__device__ int   g_off[NN + 1];
__device__ int   g_cur[NN];
__device__ int   g_csr[NE];
__device__ float g_scores[NN * CL];
__device__ int   g_goff[NG + 1];
__device__ float g_stats[2 * H];
__device__ float g_scale[H];
__device__ float g_shift[H];
__device__ float g_clust[NG * CL * H];

// ---------------- f32x2 packed helpers ----------------
__device__ __forceinline__ unsigned long long pack_dup(float a) {
    unsigned long long d;
    asm("mov.b64 %0, {%1, %1};" : "=l"(d) : "f"(a));
    return d;
}
__device__ __forceinline__ unsigned long long fma2(unsigned long long a,
                                                   unsigned long long b,
                                                   unsigned long long c) {
    unsigned long long d;
    asm("fma.rn.f32x2 %0, %1, %2, %3;" : "=l"(d) : "l"(a), "l"(b), "l"(c));
    return d;
}
__device__ __forceinline__ void unpack2(unsigned long long v, float& lo, float& hi) {
    asm("mov.b64 {%0, %1}, %2;" : "=f"(lo), "=f"(hi) : "l"(v));
}

// ---------------- CSR build ----------------
__global__ void k_deg(const int* __restrict__ dst, int e) {
    int i = blockIdx.x * blockDim.x + threadIdx.x;
    if (i < e) atomicAdd(&g_deg[dst[i]], 1);
}

// single block, 1024 threads: exclusive scan of g_deg -> g_off, copy to g_cur
__global__ void k_scan(int n) {
    __shared__ int wsum[32];
    __shared__ int carry;
    int t = threadIdx.x;
    if (t == 0) carry = 0;
    __syncthreads();
    for (int base = 0; base < n; base += 1024) {
        int i = base + t;
        int v = (i < n) ? g_deg[i] : 0;
        int x = v;
        #pragma unroll
        for (int d = 1; d < 32; d <<= 1) {
            int y = __shfl_up_sync(0xffffffffu, x, d);
            if ((t & 31) >= d) x += y;
        }
        if ((t & 31) == 31) wsum[t >> 5] = x;
        __syncthreads();
        if (t < 32) {
            int z = wsum[t];
            #pragma unroll
            for (int d = 1; d < 32; d <<= 1) {
                int y = __shfl_up_sync(0xffffffffu, z, d);
                if (t >= d) z += y;
            }
            wsum[t] = z;   // inclusive warp-sum scan
        }
        __syncthreads();
        int incl = x + ((t >= 32) ? wsum[(t >> 5) - 1] : 0);
        int excl = incl - v + carry;
        if (i < n) { g_off[i] = excl; g_cur[i] = excl; }
        __syncthreads();
        if (t == 1023) carry += incl;  // incl at t=1023 == block total
        __syncthreads();
    }
    if (t == 0) g_off[n] = carry;
}

__global__ void k_scatter(const int* __restrict__ src, const int* __restrict__ dst, int e) {
    int i = blockIdx.x * blockDim.x + threadIdx.x;
    if (i < e) {
        int d = dst[i];
        int p = atomicAdd(&g_cur[d], 1);
        g_csr[p] = src[i];
    }
}

// ---------------- embedding gather ----------------
__global__ void k_embed(const float* __restrict__ emb, const int* __restrict__ degidx, int n) {
    int i = blockIdx.x * blockDim.x + threadIdx.x;  // over n*32 float4s
    if (i < n * 32) {
        int node = i >> 5, q = i & 31;
        int d = degidx[node];
        ((float4*)g_x)[i] = ((const float4*)(emb + (size_t)d * H))[q];
    }
}

// graph segment offsets from sorted batch
__global__ void k_goff(const int* __restrict__ batch, int n) {
    int i = blockIdx.x * blockDim.x + threadIdx.x;
    if (i < n) {
        int b  = batch[i];
        int bp = (i == 0) ? -1 : batch[i - 1];
        for (int g = bp + 1; g <= b; g++) g_goff[g] = i;
        if (i == n - 1) {
            for (int g = b + 1; g <= NG; g++) g_goff[g] = n;
        }
    }
}

// ---------------- mean aggregation: one warp per node, 2-way edge unroll ----------------
__global__ void __launch_bounds__(256) k_agg(int n) {
    int w    = (blockIdx.x * blockDim.x + threadIdx.x) >> 5;
    int lane = threadIdx.x & 31;
    if (w >= n) return;
    int beg = g_off[w], end = g_off[w + 1];
    float4 acc0 = make_float4(0.f, 0.f, 0.f, 0.f);
    float4 acc1 = make_float4(0.f, 0.f, 0.f, 0.f);
    int e = beg;
    for (; e + 1 < end; e += 2) {
        int s0 = g_csr[e], s1 = g_csr[e + 1];
        float4 v0 = *(const float4*)&g_x[(size_t)s0 * H + lane * 4];
        float4 v1 = *(const float4*)&g_x[(size_t)s1 * H + lane * 4];
        acc0.x += v0.x; acc0.y += v0.y; acc0.z += v0.z; acc0.w += v0.w;
        acc1.x += v1.x; acc1.y += v1.y; acc1.z += v1.z; acc1.w += v1.w;
    }
    if (e < end) {
        int s = g_csr[e];
        float4 v = *(const float4*)&g_x[(size_t)s * H + lane * 4];
        acc0.x += v.x; acc0.y += v.y; acc0.z += v.z; acc0.w += v.w;
    }
    acc0.x += acc1.x; acc0.y += acc1.y; acc0.z += acc1.z; acc0.w += acc1.w;
    int cnt = end - beg;
    float inv = 1.f / (float)(cnt > 1 ? cnt : 1);
    acc0.x *= inv; acc0.y *= inv; acc0.z *= inv; acc0.w *= inv;
    *(float4*)&g_m[(size_t)w * H + lane * 4] = acc0;
}

// ---------------- fused dual GEMM + bias + batchnorm partial stats ----------------
// Y = M @ Wl + X @ Wr + bl ; accumulate per-column sum/sumsq into g_stats
// Inner product uses packed f32x2 FMA (FFMA2): 2 FMAs per issue slot.
#define GEMM_SMEM ((256 * 128 + 16 * 132 + 256) * 4)
__global__ void __launch_bounds__(256) k_gemm(const float* __restrict__ Wl,
                                              const float* __restrict__ Wr,
                                              const float* __restrict__ bl, int n) {
    extern __shared__ float sm[];
    float* Ws   = sm;                       // [256][128]  (Wl rows 0..127, Wr rows 128..255)
    float* As   = sm + 256 * 128;           // [16][132]   transposed A tile
    float* sred = As + 16 * 132;            // [256]       col sums / sumsq

    int t = threadIdx.x;
    {
        const float4* wl4 = (const float4*)Wl;
        const float4* wr4 = (const float4*)Wr;
        float4* ws4 = (float4*)Ws;
        #pragma unroll
        for (int i = t; i < 128 * 128 / 4; i += 256) {
            ws4[i]                 = wl4[i];
            ws4[128 * 128 / 4 + i] = wr4[i];
        }
    }
    sred[t] = 0.f;

    int rowBase = blockIdx.x * 128;
    int ty = t >> 4, tx = t & 15;

    unsigned long long acc2[8][4];
    #pragma unroll
    for (int i = 0; i < 8; i++)
        #pragma unroll
        for (int jp = 0; jp < 4; jp++) acc2[i][jp] = 0ULL;

    int r = t >> 1, kh = (t & 1) * 8;

    for (int k0 = 0; k0 < 256; k0 += 16) {
        __syncthreads();
        const float* A = (k0 < 128) ? g_m : g_x;
        int grow = rowBase + r;
        float4 v0 = make_float4(0.f, 0.f, 0.f, 0.f);
        float4 v1 = make_float4(0.f, 0.f, 0.f, 0.f);
        if (grow < n) {
            const float4* p = (const float4*)&A[(size_t)grow * H + (k0 & 127) + kh];
            v0 = p[0]; v1 = p[1];
        }
        As[(kh + 0) * 132 + r] = v0.x; As[(kh + 1) * 132 + r] = v0.y;
        As[(kh + 2) * 132 + r] = v0.z; As[(kh + 3) * 132 + r] = v0.w;
        As[(kh + 4) * 132 + r] = v1.x; As[(kh + 5) * 132 + r] = v1.y;
        As[(kh + 6) * 132 + r] = v1.z; As[(kh + 7) * 132 + r] = v1.w;
        __syncthreads();

        #pragma unroll
        for (int kk = 0; kk < 16; kk++) {
            float4 a0 = *(const float4*)&As[kk * 132 + ty * 8];
            float4 a1 = *(const float4*)&As[kk * 132 + ty * 8 + 4];
            const unsigned long long* wp =
                (const unsigned long long*)&Ws[(k0 + kk) * 128 + tx * 8];
            unsigned long long w0 = wp[0], w1 = wp[1], w2 = wp[2], w3 = wp[3];
            float a[8] = {a0.x, a0.y, a0.z, a0.w, a1.x, a1.y, a1.z, a1.w};
            #pragma unroll
            for (int i = 0; i < 8; i++) {
                unsigned long long ad = pack_dup(a[i]);
                acc2[i][0] = fma2(ad, w0, acc2[i][0]);
                acc2[i][1] = fma2(ad, w1, acc2[i][1]);
                acc2[i][2] = fma2(ad, w2, acc2[i][2]);
                acc2[i][3] = fma2(ad, w3, acc2[i][3]);
            }
        }
    }
    __syncthreads();

    float b[8];
    #pragma unroll
    for (int j = 0; j < 8; j++) b[j] = bl[tx * 8 + j];

    float cs[8], cq[8];
    #pragma unroll
    for (int j = 0; j < 8; j++) { cs[j] = 0.f; cq[j] = 0.f; }

    #pragma unroll
    for (int i = 0; i < 8; i++) {
        int grow = rowBase + ty * 8 + i;
        if (grow < n) {
            float y[8];
            #pragma unroll
            for (int jp = 0; jp < 4; jp++)
                unpack2(acc2[i][jp], y[2 * jp], y[2 * jp + 1]);
            #pragma unroll
            for (int j = 0; j < 8; j++) {
                y[j] += b[j];
                cs[j] += y[j];
                cq[j] += y[j] * y[j];
            }
            float* dstp = &g_y[(size_t)grow * H + tx * 8];
            float4 o0 = {y[0], y[1], y[2], y[3]};
            float4 o1 = {y[4], y[5], y[6], y[7]};
            *(float4*)dstp       = o0;
            *(float4*)(dstp + 4) = o1;
        }
    }
    #pragma unroll
    for (int j = 0; j < 8; j++) {
        atomicAdd(&sred[tx * 8 + j],       cs[j]);
        atomicAdd(&sred[128 + tx * 8 + j], cq[j]);
    }
    __syncthreads();
    if (t < 128) {
        atomicAdd(&g_stats[t],       sred[t]);
        atomicAdd(&g_stats[128 + t], sred[128 + t]);
    }
}

__global__ void k_statfinal(const float* __restrict__ gamma, const float* __restrict__ beta, int n) {
    int c = threadIdx.x;  // 128
    float s = g_stats[c], s2 = g_stats[128 + c];
    float invn = 1.f / (float)n;
    float mu  = s * invn;
    float var = s2 * invn - mu * mu;
    float rs  = rsqrtf(var + 1e-5f);
    float sc  = rs * gamma[c];
    g_scale[c] = sc;
    g_shift[c] = beta[c] - mu * sc;
    g_stats[c] = 0.f;          // reset for next layer / next replay
    g_stats[128 + c] = 0.f;
}

__global__ void k_norm(int n) {
    int i = blockIdx.x * blockDim.x + threadIdx.x;  // over n*32 float4s
    if (i < n * 32) {
        int q = i & 31;
        float4 y  = ((const float4*)g_y)[i];
        float4 sc = *(const float4*)&g_scale[q * 4];
        float4 sh = *(const float4*)&g_shift[q * 4];
        float4 r;
        r.x = fmaxf(y.x * sc.x + sh.x, 0.f);
        r.y = fmaxf(y.y * sc.y + sh.y, 0.f);
        r.z = fmaxf(y.z * sc.z + sh.z, 0.f);
        r.w = fmaxf(y.w * sc.w + sh.w, 0.f);
        ((float4*)g_x)[i] = r;
    }
}

// ---------------- attention scores: 32 nodes / block staged in smem ----------------
__global__ void __launch_bounds__(128) k_scores(const float* __restrict__ attn_W,
                                                const float* __restrict__ attn_b, int n) {
    __shared__ float Xs[32 * 132];
    __shared__ float Ws[128 * CL];
    __shared__ float bs[CL];
    int t = threadIdx.x;
    for (int i = t; i < 128 * CL; i += 128) Ws[i] = attn_W[i];
    if (t < CL) bs[t] = attn_b[t];
    int nb = blockIdx.x * 32;
    for (int i = t; i < 1024; i += 128) {   // 32 rows * 32 float4
        int row = i >> 5, q = i & 31;
        float4 v = make_float4(0.f, 0.f, 0.f, 0.f);
        int node = nb + row;
        if (node < n) v = *(const float4*)&g_x[(size_t)node * H + q * 4];
        *(float4*)&Xs[row * 132 + q * 4] = v;
    }
    __syncthreads();
    int c = t & 15, ng = t >> 4;            // 8 groups of 4 nodes x 16 clusters
    float a0 = bs[c], a1 = bs[c], a2 = bs[c], a3 = bs[c];
    const float* x0 = &Xs[(ng * 4 + 0) * 132];
    const float* x1 = &Xs[(ng * 4 + 1) * 132];
    const float* x2 = &Xs[(ng * 4 + 2) * 132];
    const float* x3 = &Xs[(ng * 4 + 3) * 132];
    #pragma unroll
    for (int k = 0; k < 128; k += 4) {
        float w0 = Ws[(k + 0) * CL + c], w1 = Ws[(k + 1) * CL + c];
        float w2 = Ws[(k + 2) * CL + c], w3 = Ws[(k + 3) * CL + c];
        float4 v;
        v = *(const float4*)&x0[k]; a0 += v.x * w0 + v.y * w1 + v.z * w2 + v.w * w3;
        v = *(const float4*)&x1[k]; a1 += v.x * w0 + v.y * w1 + v.z * w2 + v.w * w3;
        v = *(const float4*)&x2[k]; a2 += v.x * w0 + v.y * w1 + v.z * w2 + v.w * w3;
        v = *(const float4*)&x3[k]; a3 += v.x * w0 + v.y * w1 + v.z * w2 + v.w * w3;
    }
    int node = nb + ng * 4;
    if (node + 0 < n) g_scores[(size_t)(node + 0) * CL + c] = a0;
    if (node + 1 < n) g_scores[(size_t)(node + 1) * CL + c] = a1;
    if (node + 2 < n) g_scores[(size_t)(node + 2) * CL + c] = a2;
    if (node + 3 < n) g_scores[(size_t)(node + 3) * CL + c] = a3;
}

// ---------------- per-graph softmax pooling: one block per graph ----------------
__global__ void __launch_bounds__(256) k_pool() {
    int g = blockIdx.x, t = threadIdx.x, lane = t & 31, wid = t >> 5;
    int beg = g_goff[g], end = g_goff[g + 1];
    __shared__ float red[CL][9];
    __shared__ float smax[CL], sinv[CL];
    float lv[CL];
    #pragma unroll
    for (int c = 0; c < CL; c++) lv[c] = -1e30f;
    for (int i = beg + t; i < end; i += 256) {
        const float4* sp = (const float4*)&g_scores[(size_t)i * CL];
        #pragma unroll
        for (int q = 0; q < 4; q++) {
            float4 s = sp[q];
            lv[4 * q + 0] = fmaxf(lv[4 * q + 0], s.x);
            lv[4 * q + 1] = fmaxf(lv[4 * q + 1], s.y);
            lv[4 * q + 2] = fmaxf(lv[4 * q + 2], s.z);
            lv[4 * q + 3] = fmaxf(lv[4 * q + 3], s.w);
        }
    }
    #pragma unroll
    for (int c = 0; c < CL; c++) {
        float v = lv[c];
        #pragma unroll
        for (int o = 16; o; o >>= 1) v = fmaxf(v, __shfl_xor_sync(0xffffffffu, v, o));
        if (lane == 0) red[c][wid] = v;
    }
    __syncthreads();
    if (t < CL) {
        float v = red[t][0];
        #pragma unroll
        for (int w = 1; w < 8; w++) v = fmaxf(v, red[t][w]);
        smax[t] = v;
    }
    __syncthreads();
    #pragma unroll
    for (int c = 0; c < CL; c++) lv[c] = 0.f;
    for (int i = beg + t; i < end; i += 256) {
        const float4* sp = (const float4*)&g_scores[(size_t)i * CL];
        #pragma unroll
        for (int q = 0; q < 4; q++) {
            float4 s = sp[q];
            lv[4 * q + 0] += expf(s.x - smax[4 * q + 0]);
            lv[4 * q + 1] += expf(s.y - smax[4 * q + 1]);
            lv[4 * q + 2] += expf(s.z - smax[4 * q + 2]);
            lv[4 * q + 3] += expf(s.w - smax[4 * q + 3]);
        }
    }
    #pragma unroll
    for (int c = 0; c < CL; c++) {
        float v = lv[c];
        #pragma unroll
        for (int o = 16; o; o >>= 1) v += __shfl_xor_sync(0xffffffffu, v, o);
        if (lane == 0) red[c][wid] = v;
    }
    __syncthreads();
    if (t < CL) {
        float v = 0.f;
        #pragma unroll
        for (int w = 0; w < 8; w++) v += red[t][w];
        sinv[t] = 1.f / v;
    }
    __syncthreads();
    int c = t >> 4, h0 = (t & 15) * 8;
    float acc[8];
    #pragma unroll
    for (int j = 0; j < 8; j++) acc[j] = 0.f;
    float mx = smax[c], iv = sinv[c];
    for (int i = beg; i < end; i++) {
        float w = expf(g_scores[(size_t)i * CL + c] - mx) * iv;
        const float* xp = &g_x[(size_t)i * H + h0];
        float4 v0 = *(const float4*)xp;
        float4 v1 = *(const float4*)(xp + 4);
        acc[0] += w * v0.x; acc[1] += w * v0.y; acc[2] += w * v0.z; acc[3] += w * v0.w;
        acc[4] += w * v1.x; acc[5] += w * v1.y; acc[6] += w * v1.z; acc[7] += w * v1.w;
    }
    float* op = &g_clust[((size_t)g * CL + c) * H + h0];
    float4 o0 = {acc[0], acc[1], acc[2], acc[3]};
    float4 o1 = {acc[4], acc[5], acc[6], acc[7]};
    *(float4*)op       = o0;
    *(float4*)(op + 4) = o1;
}

// ---------------- final projection: clust[1024,128] @ out_W[128,128] ----------------
__global__ void __launch_bounds__(256) k_out(const float* __restrict__ W,
                                             const float* __restrict__ b,
                                             float* __restrict__ out) {
    int row  = blockIdx.x * 8 + (threadIdx.x >> 5);
    int lane = threadIdx.x & 31;
    if (row >= NG * CL) return;
    float4 acc = *(const float4*)&b[lane * 4];
    const float* cl = &g_clust[(size_t)row * H];
    #pragma unroll 4
    for (int k = 0; k < H; k++) {
        float c  = cl[k];
        float4 w = *(const float4*)&W[(size_t)k * ODIM + lane * 4];
        acc.x += c * w.x; acc.y += c * w.y; acc.z += c * w.z; acc.w += c * w.w;
    }
    *(float4*)&out[(size_t)row * ODIM + lane * 4] = acc;
}

// ---------------- launch ----------------
extern "C" void kernel_launch(void* const* d_in, const int* in_sizes, int n_in,
                              void* d_out, int out_size) {
    const float* emb    = (const float*)d_in[0];
    const float* Wl     = (const float*)d_in[1];
    const float* bl     = (const float*)d_in[2];
    const float* Wr     = (const float*)d_in[3];
    const float* gamma  = (const float*)d_in[4];
    const float* beta   = (const float*)d_in[5];
    const float* attn_W = (const float*)d_in[6];
    const float* attn_b = (const float*)d_in[7];
    const float* out_W  = (const float*)d_in[8];
    const float* out_b  = (const float*)d_in[9];
    const int* deg_idx  = (const int*)d_in[10];
    const int* edge     = (const int*)d_in[11];
    const int* batch    = (const int*)d_in[12];
    float* out          = (float*)d_out;

    const int n = NN, e = NE;

    cudaFuncSetAttribute(k_gemm, cudaFuncAttributeMaxDynamicSharedMemorySize, GEMM_SMEM);

    void* degp = nullptr;
    cudaGetSymbolAddress(&degp, g_deg);
    cudaMemsetAsync(degp, 0, NN * sizeof(int));

    k_deg<<<(e + 255) / 256, 256>>>(edge + e, e);
    k_scan<<<1, 1024>>>(n);
    k_scatter<<<(e + 255) / 256, 256>>>(edge, edge + e, e);
    k_embed<<<(n * 32 + 255) / 256, 256>>>(emb, deg_idx, n);
    k_goff<<<(n + 255) / 256, 256>>>(batch, n);

    for (int l = 0; l < 3; l++) {
        k_agg<<<(n * 32 + 255) / 256, 256>>>(n);
        k_gemm<<<(n + 127) / 128, 256, GEMM_SMEM>>>(Wl + l * H * H, Wr + l * H * H,
                                                    bl + l * H, n);
        k_statfinal<<<1, 128>>>(gamma + l * H, beta + l * H, n);
        k_norm<<<(n * 32 + 255) / 256, 256>>>(n);
    }

    k_scores<<<(n + 31) / 32, 128>>>(attn_W, attn_b, n);
    k_pool<<<NG, 256>>>();
    k_out<<<(NG * CL) / 8, 256>>>(out_W, out_b, out);
}

// round 4
// speedup vs baseline: 1.5262x; 1.3981x over previous
#include <cuda_runtime.h>
#include <cuda_bf16.h>
#include <cstdint>

#define NN 50000
#define NE 800000
#define NG 64
#define H  128
#define CL 16
#define ODIM 128

// ---------------- scratch (device globals; no allocation allowed) ----------------
__device__ float g_x[NN * H];
__device__ float g_m[NN * H];
__device__ float g_y[NN * H];
__device__ int   g_deg[NN];
__device__ int   g_off[NN + 1];
__device__ int   g_cur[NN];
__device__ int   g_csr[NE];
__device__ float g_scores[NN * CL];
__device__ int   g_goff[NG + 1];
__device__ float g_stats[2 * H];
__device__ float g_scale[H];
__device__ float g_shift[H];
__device__ float g_clust[NG * CL * H];
// weights pre-split into bf16 hi/lo, packed as u32 pairs along k:
// layout [layer][n][kpair]  (kpair = k/2, 128 pairs, k<128 -> Wl^T, k>=128 -> Wr^T)
__device__ uint32_t g_wth[3 * 128 * 128];
__device__ uint32_t g_wtl[3 * 128 * 128];

// ---------------- bf16 split helpers ----------------
__device__ __forceinline__ void split_pack(float x, float y, uint32_t& hi, uint32_t& lo) {
    __nv_bfloat16 hx = __float2bfloat16(x);
    __nv_bfloat16 hy = __float2bfloat16(y);
    float rx = x - __bfloat162float(hx);
    float ry = y - __bfloat162float(hy);
    __nv_bfloat16 lx = __float2bfloat16(rx);
    __nv_bfloat16 ly = __float2bfloat16(ry);
    hi = ((uint32_t)__bfloat16_as_ushort(hy) << 16) | (uint32_t)__bfloat16_as_ushort(hx);
    lo = ((uint32_t)__bfloat16_as_ushort(ly) << 16) | (uint32_t)__bfloat16_as_ushort(lx);
}

__device__ __forceinline__ void mma_bf16(float* c, const uint32_t* a, const uint32_t* b) {
    asm volatile(
        "mma.sync.aligned.m16n8k16.row.col.f32.bf16.bf16.f32 "
        "{%0,%1,%2,%3}, {%4,%5,%6,%7}, {%8,%9}, {%0,%1,%2,%3};"
        : "+f"(c[0]), "+f"(c[1]), "+f"(c[2]), "+f"(c[3])
        : "r"(a[0]), "r"(a[1]), "r"(a[2]), "r"(a[3]), "r"(b[0]), "r"(b[1]));
}

// ---------------- CSR build ----------------
__global__ void k_deg(const int* __restrict__ dst, int e) {
    int i = blockIdx.x * blockDim.x + threadIdx.x;
    if (i < e) atomicAdd(&g_deg[dst[i]], 1);
}

// single block, 1024 threads, 4 elems/thread: exclusive scan g_deg -> g_off, copy g_cur
__global__ void k_scan(int n) {
    __shared__ int wsum[32];
    __shared__ int carry;
    int t = threadIdx.x;
    if (t == 0) carry = 0;
    __syncthreads();
    for (int base = 0; base < n; base += 4096) {
        int i = base + t * 4;
        int4 v4 = make_int4(0, 0, 0, 0);
        if (i + 3 < n) v4 = *(const int4*)&g_deg[i];
        else {
            if (i + 0 < n) v4.x = g_deg[i + 0];
            if (i + 1 < n) v4.y = g_deg[i + 1];
            if (i + 2 < n) v4.z = g_deg[i + 2];
            if (i + 3 < n) v4.w = g_deg[i + 3];
        }
        int p1 = v4.x, p2 = p1 + v4.y, p3 = p2 + v4.z, v = p3 + v4.w;
        int x = v;
        #pragma unroll
        for (int d = 1; d < 32; d <<= 1) {
            int y = __shfl_up_sync(0xffffffffu, x, d);
            if ((t & 31) >= d) x += y;
        }
        if ((t & 31) == 31) wsum[t >> 5] = x;
        __syncthreads();
        if (t < 32) {
            int z = wsum[t];
            #pragma unroll
            for (int d = 1; d < 32; d <<= 1) {
                int y = __shfl_up_sync(0xffffffffu, z, d);
                if (t >= d) z += y;
            }
            wsum[t] = z;
        }
        __syncthreads();
        int incl = x + ((t >= 32) ? wsum[(t >> 5) - 1] : 0);
        int excl = incl - v + carry;
        int4 o = make_int4(excl, excl + p1, excl + p2, excl + p3);
        if (i + 3 < n) {
            *(int4*)&g_off[i] = o;
            *(int4*)&g_cur[i] = o;
        } else {
            if (i + 0 < n) { g_off[i + 0] = o.x; g_cur[i + 0] = o.x; }
            if (i + 1 < n) { g_off[i + 1] = o.y; g_cur[i + 1] = o.y; }
            if (i + 2 < n) { g_off[i + 2] = o.z; g_cur[i + 2] = o.z; }
            if (i + 3 < n) { g_off[i + 3] = o.w; g_cur[i + 3] = o.w; }
        }
        __syncthreads();
        if (t == 1023) carry += incl;
        __syncthreads();
    }
    if (t == 0) g_off[n] = carry;
}

__global__ void k_scatter(const int* __restrict__ src, const int* __restrict__ dst, int e) {
    int i = blockIdx.x * blockDim.x + threadIdx.x;
    if (i < e) {
        int d = dst[i];
        int p = atomicAdd(&g_cur[d], 1);
        g_csr[p] = src[i];
    }
}

// ---------------- embedding gather ----------------
__global__ void k_embed(const float* __restrict__ emb, const int* __restrict__ degidx, int n) {
    int i = blockIdx.x * blockDim.x + threadIdx.x;
    if (i < n * 32) {
        int node = i >> 5, q = i & 31;
        int d = degidx[node];
        ((float4*)g_x)[i] = ((const float4*)(emb + (size_t)d * H))[q];
    }
}

__global__ void k_goff(const int* __restrict__ batch, int n) {
    int i = blockIdx.x * blockDim.x + threadIdx.x;
    if (i < n) {
        int b  = batch[i];
        int bp = (i == 0) ? -1 : batch[i - 1];
        for (int g = bp + 1; g <= b; g++) g_goff[g] = i;
        if (i == n - 1) {
            for (int g = b + 1; g <= NG; g++) g_goff[g] = n;
        }
    }
}

// ---------------- weight prep: transpose + bf16 hi/lo split ----------------
// g_wt*(l, n, kpair): k<128 from Wl[l][k][n], k>=128 from Wr[l][k-128][n]
__global__ void k_prep(const float* __restrict__ Wl, const float* __restrict__ Wr) {
    int i = blockIdx.x * blockDim.x + threadIdx.x;   // over 3*128*128 k-pairs
    if (i < 3 * 128 * 128) {
        int l = i >> 14, r = i & 16383, nn = r >> 7, kp = r & 127;
        int k = kp * 2;
        float v0, v1;
        if (k < 128) {
            v0 = Wl[l * 16384 + k * 128 + nn];
            v1 = Wl[l * 16384 + (k + 1) * 128 + nn];
        } else {
            v0 = Wr[l * 16384 + (k - 128) * 128 + nn];
            v1 = Wr[l * 16384 + (k - 127) * 128 + nn];
        }
        uint32_t hi, lo;
        split_pack(v0, v1, hi, lo);
        g_wth[i] = hi;
        g_wtl[i] = lo;
    }
}

// ---------------- mean aggregation: one warp per node, 2-way edge unroll ----------------
__global__ void __launch_bounds__(256) k_agg(int n) {
    int w    = (blockIdx.x * blockDim.x + threadIdx.x) >> 5;
    int lane = threadIdx.x & 31;
    if (w >= n) return;
    int beg = g_off[w], end = g_off[w + 1];
    float4 acc0 = make_float4(0.f, 0.f, 0.f, 0.f);
    float4 acc1 = make_float4(0.f, 0.f, 0.f, 0.f);
    int e = beg;
    for (; e + 1 < end; e += 2) {
        int s0 = g_csr[e], s1 = g_csr[e + 1];
        float4 v0 = *(const float4*)&g_x[(size_t)s0 * H + lane * 4];
        float4 v1 = *(const float4*)&g_x[(size_t)s1 * H + lane * 4];
        acc0.x += v0.x; acc0.y += v0.y; acc0.z += v0.z; acc0.w += v0.w;
        acc1.x += v1.x; acc1.y += v1.y; acc1.z += v1.z; acc1.w += v1.w;
    }
    if (e < end) {
        int s = g_csr[e];
        float4 v = *(const float4*)&g_x[(size_t)s * H + lane * 4];
        acc0.x += v.x; acc0.y += v.y; acc0.z += v.z; acc0.w += v.w;
    }
    acc0.x += acc1.x; acc0.y += acc1.y; acc0.z += acc1.z; acc0.w += acc1.w;
    int cnt = end - beg;
    float inv = 1.f / (float)(cnt > 1 ? cnt : 1);
    acc0.x *= inv; acc0.y *= inv; acc0.z *= inv; acc0.w *= inv;
    *(float4*)&g_m[(size_t)w * H + lane * 4] = acc0;
}

// ---------------- mma.sync bf16-split GEMM ----------------
// Y[128,128] = [M|X](K=256) @ W^T + bias ; fused batchnorm partial stats.
// smem: 4 bf16 planes [128][72] (Ah, Al, Bh, Bl) + sred[256] + sbias[128]
#define WST 72
#define PLANE (128 * WST)
#define GEMM_SMEM_MMA (4 * PLANE * 2 + 256 * 4 + 128 * 4)

__global__ void __launch_bounds__(256, 2) k_gemm_mma(const float* __restrict__ bl,
                                                     int layer, int n) {
    extern __shared__ char smraw[];
    __nv_bfloat16* Ah = (__nv_bfloat16*)smraw;
    __nv_bfloat16* Al = Ah + PLANE;
    __nv_bfloat16* Bh = Al + PLANE;
    __nv_bfloat16* Bl = Bh + PLANE;
    float* sred  = (float*)(Bl + PLANE);   // [256]
    float* sbias = sred + 256;             // [128]

    int t = threadIdx.x, lane = t & 31, wid = t >> 5;
    int gq = lane >> 2, tig = lane & 3;
    int rowBase = blockIdx.x * 128;
    int m0 = (wid >> 2) * 64, n0 = (wid & 3) * 32;
    const uint32_t* wth = g_wth + layer * 16384;
    const uint32_t* wtl = g_wtl + layer * 16384;

    if (t < 128) sbias[t] = bl[t];
    sred[t] = 0.f;   // t < 256 always

    float acc[4][4][4];
    #pragma unroll
    for (int mt = 0; mt < 4; mt++)
        #pragma unroll
        for (int nt = 0; nt < 4; nt++)
            #pragma unroll
            for (int q = 0; q < 4; q++) acc[mt][nt][q] = 0.f;

    for (int chunk = 0; chunk < 4; chunk++) {
        const float* Asrc = (chunk < 2) ? g_m : g_x;
        int k0 = (chunk & 1) * 64;
        __syncthreads();
        // stage 128 rows x 32 k-pairs for A (convert) and B (pre-split)
        #pragma unroll
        for (int it = 0; it < 16; it++) {
            int f = t + it * 256;            // 0..4095
            int row = f >> 5, kp = f & 31;
            // A
            float2 va = make_float2(0.f, 0.f);
            int grow = rowBase + row;
            if (grow < n) va = *(const float2*)&Asrc[(size_t)grow * 128 + k0 + kp * 2];
            uint32_t hi, lo;
            split_pack(va.x, va.y, hi, lo);
            *(uint32_t*)&Ah[row * WST + kp * 2] = hi;
            *(uint32_t*)&Al[row * WST + kp * 2] = lo;
            // B
            *(uint32_t*)&Bh[row * WST + kp * 2] = wth[row * 128 + chunk * 32 + kp];
            *(uint32_t*)&Bl[row * WST + kp * 2] = wtl[row * 128 + chunk * 32 + kp];
        }
        __syncthreads();

        #pragma unroll
        for (int ks = 0; ks < 4; ks++) {
            int kb = ks * 16;
            uint32_t bh[4][2], blo[4][2];
            #pragma unroll
            for (int nt = 0; nt < 4; nt++) {
                int brow = n0 + nt * 8 + gq;
                int kc = kb + tig * 2;
                bh[nt][0]  = *(const uint32_t*)&Bh[brow * WST + kc];
                bh[nt][1]  = *(const uint32_t*)&Bh[brow * WST + kc + 8];
                blo[nt][0] = *(const uint32_t*)&Bl[brow * WST + kc];
                blo[nt][1] = *(const uint32_t*)&Bl[brow * WST + kc + 8];
            }
            #pragma unroll
            for (int mt = 0; mt < 4; mt++) {
                int arow = m0 + mt * 16 + gq;
                int kc = kb + tig * 2;
                uint32_t ah[4], al[4];
                ah[0] = *(const uint32_t*)&Ah[arow * WST + kc];
                ah[1] = *(const uint32_t*)&Ah[(arow + 8) * WST + kc];
                ah[2] = *(const uint32_t*)&Ah[arow * WST + kc + 8];
                ah[3] = *(const uint32_t*)&Ah[(arow + 8) * WST + kc + 8];
                al[0] = *(const uint32_t*)&Al[arow * WST + kc];
                al[1] = *(const uint32_t*)&Al[(arow + 8) * WST + kc];
                al[2] = *(const uint32_t*)&Al[arow * WST + kc + 8];
                al[3] = *(const uint32_t*)&Al[(arow + 8) * WST + kc + 8];
                #pragma unroll
                for (int nt = 0; nt < 4; nt++) {
                    mma_bf16(acc[mt][nt], ah, bh[nt]);   // hi*hi
                    mma_bf16(acc[mt][nt], ah, blo[nt]);  // hi*lo
                    mma_bf16(acc[mt][nt], al, bh[nt]);   // lo*hi
                }
            }
        }
    }

    // epilogue: bias add, store, batchnorm partial stats
    float cs[4][2], cq[4][2];
    #pragma unroll
    for (int nt = 0; nt < 4; nt++) { cs[nt][0] = cs[nt][1] = cq[nt][0] = cq[nt][1] = 0.f; }
    #pragma unroll
    for (int mt = 0; mt < 4; mt++) {
        #pragma unroll
        for (int r = 0; r < 2; r++) {
            int row = rowBase + m0 + mt * 16 + gq + r * 8;
            if (row < n) {
                #pragma unroll
                for (int nt = 0; nt < 4; nt++) {
                    int col = n0 + nt * 8 + tig * 2;
                    float y0 = acc[mt][nt][r * 2 + 0] + sbias[col];
                    float y1 = acc[mt][nt][r * 2 + 1] + sbias[col + 1];
                    *(float2*)&g_y[(size_t)row * 128 + col] = make_float2(y0, y1);
                    cs[nt][0] += y0; cs[nt][1] += y1;
                    cq[nt][0] += y0 * y0; cq[nt][1] += y1 * y1;
                }
            }
        }
    }
    #pragma unroll
    for (int nt = 0; nt < 4; nt++) {
        #pragma unroll
        for (int j = 0; j < 2; j++) {
            float s = cs[nt][j], q = cq[nt][j];
            #pragma unroll
            for (int o = 4; o < 32; o <<= 1) {
                s += __shfl_xor_sync(0xffffffffu, s, o);
                q += __shfl_xor_sync(0xffffffffu, q, o);
            }
            if (gq == 0) {
                int col = n0 + nt * 8 + tig * 2 + j;
                atomicAdd(&sred[col], s);
                atomicAdd(&sred[128 + col], q);
            }
        }
    }
    __syncthreads();
    if (t < 128) {
        atomicAdd(&g_stats[t],       sred[t]);
        atomicAdd(&g_stats[128 + t], sred[128 + t]);
    }
}

__global__ void k_statfinal(const float* __restrict__ gamma, const float* __restrict__ beta, int n) {
    int c = threadIdx.x;
    float s = g_stats[c], s2 = g_stats[128 + c];
    float invn = 1.f / (float)n;
    float mu  = s * invn;
    float var = s2 * invn - mu * mu;
    float rs  = rsqrtf(var + 1e-5f);
    float sc  = rs * gamma[c];
    g_scale[c] = sc;
    g_shift[c] = beta[c] - mu * sc;
    g_stats[c] = 0.f;
    g_stats[128 + c] = 0.f;
}

__global__ void k_norm(int n) {
    int i = blockIdx.x * blockDim.x + threadIdx.x;
    if (i < n * 32) {
        int q = i & 31;
        float4 y  = ((const float4*)g_y)[i];
        float4 sc = *(const float4*)&g_scale[q * 4];
        float4 sh = *(const float4*)&g_shift[q * 4];
        float4 r;
        r.x = fmaxf(y.x * sc.x + sh.x, 0.f);
        r.y = fmaxf(y.y * sc.y + sh.y, 0.f);
        r.z = fmaxf(y.z * sc.z + sh.z, 0.f);
        r.w = fmaxf(y.w * sc.w + sh.w, 0.f);
        ((float4*)g_x)[i] = r;
    }
}

// ---------------- attention scores ----------------
__global__ void __launch_bounds__(128) k_scores(const float* __restrict__ attn_W,
                                                const float* __restrict__ attn_b, int n) {
    __shared__ float Xs[32 * 132];
    __shared__ float Ws[128 * CL];
    __shared__ float bs[CL];
    int t = threadIdx.x;
    for (int i = t; i < 128 * CL; i += 128) Ws[i] = attn_W[i];
    if (t < CL) bs[t] = attn_b[t];
    int nb = blockIdx.x * 32;
    for (int i = t; i < 1024; i += 128) {
        int row = i >> 5, q = i & 31;
        float4 v = make_float4(0.f, 0.f, 0.f, 0.f);
        int node = nb + row;
        if (node < n) v = *(const float4*)&g_x[(size_t)node * H + q * 4];
        *(float4*)&Xs[row * 132 + q * 4] = v;
    }
    __syncthreads();
    int c = t & 15, ng = t >> 4;
    float a0 = bs[c], a1 = bs[c], a2 = bs[c], a3 = bs[c];
    const float* x0 = &Xs[(ng * 4 + 0) * 132];
    const float* x1 = &Xs[(ng * 4 + 1) * 132];
    const float* x2 = &Xs[(ng * 4 + 2) * 132];
    const float* x3 = &Xs[(ng * 4 + 3) * 132];
    #pragma unroll
    for (int k = 0; k < 128; k += 4) {
        float w0 = Ws[(k + 0) * CL + c], w1 = Ws[(k + 1) * CL + c];
        float w2 = Ws[(k + 2) * CL + c], w3 = Ws[(k + 3) * CL + c];
        float4 v;
        v = *(const float4*)&x0[k]; a0 += v.x * w0 + v.y * w1 + v.z * w2 + v.w * w3;
        v = *(const float4*)&x1[k]; a1 += v.x * w0 + v.y * w1 + v.z * w2 + v.w * w3;
        v = *(const float4*)&x2[k]; a2 += v.x * w0 + v.y * w1 + v.z * w2 + v.w * w3;
        v = *(const float4*)&x3[k]; a3 += v.x * w0 + v.y * w1 + v.z * w2 + v.w * w3;
    }
    int node = nb + ng * 4;
    if (node + 0 < n) g_scores[(size_t)(node + 0) * CL + c] = a0;
    if (node + 1 < n) g_scores[(size_t)(node + 1) * CL + c] = a1;
    if (node + 2 < n) g_scores[(size_t)(node + 2) * CL + c] = a2;
    if (node + 3 < n) g_scores[(size_t)(node + 3) * CL + c] = a3;
}

// ---------------- per-graph softmax pooling ----------------
__global__ void __launch_bounds__(256) k_pool() {
    int g = blockIdx.x, t = threadIdx.x, lane = t & 31, wid = t >> 5;
    int beg = g_goff[g], end = g_goff[g + 1];
    __shared__ float red[CL][9];
    __shared__ float smax[CL], sinv[CL];
    float lv[CL];
    #pragma unroll
    for (int c = 0; c < CL; c++) lv[c] = -1e30f;
    for (int i = beg + t; i < end; i += 256) {
        const float4* sp = (const float4*)&g_scores[(size_t)i * CL];
        #pragma unroll
        for (int q = 0; q < 4; q++) {
            float4 s = sp[q];
            lv[4 * q + 0] = fmaxf(lv[4 * q + 0], s.x);
            lv[4 * q + 1] = fmaxf(lv[4 * q + 1], s.y);
            lv[4 * q + 2] = fmaxf(lv[4 * q + 2], s.z);
            lv[4 * q + 3] = fmaxf(lv[4 * q + 3], s.w);
        }
    }
    #pragma unroll
    for (int c = 0; c < CL; c++) {
        float v = lv[c];
        #pragma unroll
        for (int o = 16; o; o >>= 1) v = fmaxf(v, __shfl_xor_sync(0xffffffffu, v, o));
        if (lane == 0) red[c][wid] = v;
    }
    __syncthreads();
    if (t < CL) {
        float v = red[t][0];
        #pragma unroll
        for (int w = 1; w < 8; w++) v = fmaxf(v, red[t][w]);
        smax[t] = v;
    }
    __syncthreads();
    #pragma unroll
    for (int c = 0; c < CL; c++) lv[c] = 0.f;
    for (int i = beg + t; i < end; i += 256) {
        const float4* sp = (const float4*)&g_scores[(size_t)i * CL];
        #pragma unroll
        for (int q = 0; q < 4; q++) {
            float4 s = sp[q];
            lv[4 * q + 0] += expf(s.x - smax[4 * q + 0]);
            lv[4 * q + 1] += expf(s.y - smax[4 * q + 1]);
            lv[4 * q + 2] += expf(s.z - smax[4 * q + 2]);
            lv[4 * q + 3] += expf(s.w - smax[4 * q + 3]);
        }
    }
    #pragma unroll
    for (int c = 0; c < CL; c++) {
        float v = lv[c];
        #pragma unroll
        for (int o = 16; o; o >>= 1) v += __shfl_xor_sync(0xffffffffu, v, o);
        if (lane == 0) red[c][wid] = v;
    }
    __syncthreads();
    if (t < CL) {
        float v = 0.f;
        #pragma unroll
        for (int w = 0; w < 8; w++) v += red[t][w];
        sinv[t] = 1.f / v;
    }
    __syncthreads();
    int c = t >> 4, h0 = (t & 15) * 8;
    float acc[8];
    #pragma unroll
    for (int j = 0; j < 8; j++) acc[j] = 0.f;
    float mx = smax[c], iv = sinv[c];
    for (int i = beg; i < end; i++) {
        float w = expf(g_scores[(size_t)i * CL + c] - mx) * iv;
        const float* xp = &g_x[(size_t)i * H + h0];
        float4 v0 = *(const float4*)xp;
        float4 v1 = *(const float4*)(xp + 4);
        acc[0] += w * v0.x; acc[1] += w * v0.y; acc[2] += w * v0.z; acc[3] += w * v0.w;
        acc[4] += w * v1.x; acc[5] += w * v1.y; acc[6] += w * v1.z; acc[7] += w * v1.w;
    }
    float* op = &g_clust[((size_t)g * CL + c) * H + h0];
    *(float4*)op       = make_float4(acc[0], acc[1], acc[2], acc[3]);
    *(float4*)(op + 4) = make_float4(acc[4], acc[5], acc[6], acc[7]);
}

// ---------------- final projection ----------------
__global__ void __launch_bounds__(256) k_out(const float* __restrict__ W,
                                             const float* __restrict__ b,
                                             float* __restrict__ out) {
    int row  = blockIdx.x * 8 + (threadIdx.x >> 5);
    int lane = threadIdx.x & 31;
    if (row >= NG * CL) return;
    float4 acc = *(const float4*)&b[lane * 4];
    const float* cl = &g_clust[(size_t)row * H];
    #pragma unroll 4
    for (int k = 0; k < H; k++) {
        float c  = cl[k];
        float4 w = *(const float4*)&W[(size_t)k * ODIM + lane * 4];
        acc.x += c * w.x; acc.y += c * w.y; acc.z += c * w.z; acc.w += c * w.w;
    }
    *(float4*)&out[(size_t)row * ODIM + lane * 4] = acc;
}

// ---------------- launch ----------------
extern "C" void kernel_launch(void* const* d_in, const int* in_sizes, int n_in,
                              void* d_out, int out_size) {
    const float* emb    = (const float*)d_in[0];
    const float* Wl     = (const float*)d_in[1];
    const float* bl     = (const float*)d_in[2];
    const float* Wr     = (const float*)d_in[3];
    const float* gamma  = (const float*)d_in[4];
    const float* beta   = (const float*)d_in[5];
    const float* attn_W = (const float*)d_in[6];
    const float* attn_b = (const float*)d_in[7];
    const float* out_W  = (const float*)d_in[8];
    const float* out_b  = (const float*)d_in[9];
    const int* deg_idx  = (const int*)d_in[10];
    const int* edge     = (const int*)d_in[11];
    const int* batch    = (const int*)d_in[12];
    float* out          = (float*)d_out;

    const int n = NN, e = NE;

    cudaFuncSetAttribute(k_gemm_mma, cudaFuncAttributeMaxDynamicSharedMemorySize,
                         GEMM_SMEM_MMA);

    void* degp = nullptr;
    cudaGetSymbolAddress(&degp, g_deg);
    cudaMemsetAsync(degp, 0, NN * sizeof(int));

    k_deg<<<(e + 255) / 256, 256>>>(edge + e, e);
    k_prep<<<(3 * 128 * 128 + 255) / 256, 256>>>(Wl, Wr);
    k_scan<<<1, 1024>>>(n);
    k_scatter<<<(e + 255) / 256, 256>>>(edge, edge + e, e);
    k_embed<<<(n * 32 + 255) / 256, 256>>>(emb, deg_idx, n);
    k_goff<<<(n + 255) / 256, 256>>>(batch, n);

    int gemmBlocks = (n + 127) / 128;
    for (int l = 0; l < 3; l++) {
        k_agg<<<(n * 32 + 255) / 256, 256>>>(n);
        k_gemm_mma<<<gemmBlocks, 256, GEMM_SMEM_MMA>>>(bl + l * H, l, n);
        k_statfinal<<<1, 128>>>(gamma + l * H, beta + l * H, n);
        k_norm<<<(n * 32 + 255) / 256, 256>>>(n);
    }

    k_scores<<<(n + 31) / 32, 128>>>(attn_W, attn_b, n);
    k_pool<<<NG, 256>>>();
    k_out<<<(NG * CL) / 8, 256>>>(out_W, out_b, out);
}

// round 5
// speedup vs baseline: 1.8496x; 1.2118x over previous
#include <cuda_runtime.h>
#include <cuda_bf16.h>
#include <cuda_fp16.h>
#include <cstdint>

#define NN 50000
#define NE 800000
#define NG 64
#define H  128
#define CL 16
#define ODIM 128

// ---------------- scratch (device globals; no allocation allowed) ----------------
__device__ float g_x[NN * H];
__device__ uint2 g_xh[NN * 32];     // fp16 mirror of g_x: 4 halves per uint2
__device__ float g_m[NN * H];
__device__ float g_y[NN * H];
__device__ int   g_deg[NN];
__device__ int   g_off[NN + 1];
__device__ int   g_cur[NN];
__device__ int   g_csr[NE];
__device__ float g_scores[NN * CL];
__device__ int   g_goff[NG + 1];
__device__ float g_stats[2 * H];
__device__ float g_scale[H];
__device__ float g_shift[H];
__device__ float g_clust[NG * CL * H];
__device__ float g_pmax[NG * CL];
__device__ float g_pinv[NG * CL];
// weights pre-split into bf16 hi/lo, packed as u32 pairs along k:
// layout [layer][n][kpair]  (kpair = k/2, 128 pairs, k<128 -> Wl^T, k>=128 -> Wr^T)
__device__ uint32_t g_wth[3 * 128 * 128];
__device__ uint32_t g_wtl[3 * 128 * 128];

// ---------------- helpers ----------------
__device__ __forceinline__ void split_pack(float x, float y, uint32_t& hi, uint32_t& lo) {
    __nv_bfloat16 hx = __float2bfloat16(x);
    __nv_bfloat16 hy = __float2bfloat16(y);
    float rx = x - __bfloat162float(hx);
    float ry = y - __bfloat162float(hy);
    __nv_bfloat16 lx = __float2bfloat16(rx);
    __nv_bfloat16 ly = __float2bfloat16(ry);
    hi = ((uint32_t)__bfloat16_as_ushort(hy) << 16) | (uint32_t)__bfloat16_as_ushort(hx);
    lo = ((uint32_t)__bfloat16_as_ushort(ly) << 16) | (uint32_t)__bfloat16_as_ushort(lx);
}

__device__ __forceinline__ void mma_bf16(float* c, const uint32_t* a, const uint32_t* b) {
    asm volatile(
        "mma.sync.aligned.m16n8k16.row.col.f32.bf16.bf16.f32 "
        "{%0,%1,%2,%3}, {%4,%5,%6,%7}, {%8,%9}, {%0,%1,%2,%3};"
        : "+f"(c[0]), "+f"(c[1]), "+f"(c[2]), "+f"(c[3])
        : "r"(a[0]), "r"(a[1]), "r"(a[2]), "r"(a[3]), "r"(b[0]), "r"(b[1]));
}

__device__ __forceinline__ uint2 f4_to_h4(float4 v) {
    uint2 u;
    __half2 a = __floats2half2_rn(v.x, v.y);
    __half2 b = __floats2half2_rn(v.z, v.w);
    u.x = *(uint32_t*)&a;
    u.y = *(uint32_t*)&b;
    return u;
}

// ---------------- CSR build ----------------
__global__ void k_deg(const int* __restrict__ dst, int e) {
    int i = blockIdx.x * blockDim.x + threadIdx.x;
    if (i < e) atomicAdd(&g_deg[dst[i]], 1);
}

// single block, 1024 threads, 4 elems/thread: exclusive scan g_deg -> g_off, copy g_cur
__global__ void k_scan(int n) {
    __shared__ int wsum[32];
    __shared__ int carry;
    int t = threadIdx.x;
    if (t == 0) carry = 0;
    __syncthreads();
    for (int base = 0; base < n; base += 4096) {
        int i = base + t * 4;
        int4 v4 = make_int4(0, 0, 0, 0);
        if (i + 3 < n) v4 = *(const int4*)&g_deg[i];
        else {
            if (i + 0 < n) v4.x = g_deg[i + 0];
            if (i + 1 < n) v4.y = g_deg[i + 1];
            if (i + 2 < n) v4.z = g_deg[i + 2];
            if (i + 3 < n) v4.w = g_deg[i + 3];
        }
        int p1 = v4.x, p2 = p1 + v4.y, p3 = p2 + v4.z, v = p3 + v4.w;
        int x = v;
        #pragma unroll
        for (int d = 1; d < 32; d <<= 1) {
            int y = __shfl_up_sync(0xffffffffu, x, d);
            if ((t & 31) >= d) x += y;
        }
        if ((t & 31) == 31) wsum[t >> 5] = x;
        __syncthreads();
        if (t < 32) {
            int z = wsum[t];
            #pragma unroll
            for (int d = 1; d < 32; d <<= 1) {
                int y = __shfl_up_sync(0xffffffffu, z, d);
                if (t >= d) z += y;
            }
            wsum[t] = z;
        }
        __syncthreads();
        int incl = x + ((t >= 32) ? wsum[(t >> 5) - 1] : 0);
        int excl = incl - v + carry;
        int4 o = make_int4(excl, excl + p1, excl + p2, excl + p3);
        if (i + 3 < n) {
            *(int4*)&g_off[i] = o;
            *(int4*)&g_cur[i] = o;
        } else {
            if (i + 0 < n) { g_off[i + 0] = o.x; g_cur[i + 0] = o.x; }
            if (i + 1 < n) { g_off[i + 1] = o.y; g_cur[i + 1] = o.y; }
            if (i + 2 < n) { g_off[i + 2] = o.z; g_cur[i + 2] = o.z; }
            if (i + 3 < n) { g_off[i + 3] = o.w; g_cur[i + 3] = o.w; }
        }
        __syncthreads();
        if (t == 1023) carry += incl;
        __syncthreads();
    }
    if (t == 0) g_off[n] = carry;
}

__global__ void k_scatter(const int* __restrict__ src, const int* __restrict__ dst, int e) {
    int i = blockIdx.x * blockDim.x + threadIdx.x;
    if (i < e) {
        int d = dst[i];
        int p = atomicAdd(&g_cur[d], 1);
        g_csr[p] = src[i];
    }
}

// ---------------- embedding gather (fp32 + fp16 mirror) ----------------
__global__ void k_embed(const float* __restrict__ emb, const int* __restrict__ degidx, int n) {
    int i = blockIdx.x * blockDim.x + threadIdx.x;
    if (i < n * 32) {
        int node = i >> 5, q = i & 31;
        int d = degidx[node];
        float4 v = ((const float4*)(emb + (size_t)d * H))[q];
        ((float4*)g_x)[i] = v;
        g_xh[i] = f4_to_h4(v);
    }
}

__global__ void k_goff(const int* __restrict__ batch, int n) {
    int i = blockIdx.x * blockDim.x + threadIdx.x;
    if (i < n) {
        int b  = batch[i];
        int bp = (i == 0) ? -1 : batch[i - 1];
        for (int g = bp + 1; g <= b; g++) g_goff[g] = i;
        if (i == n - 1) {
            for (int g = b + 1; g <= NG; g++) g_goff[g] = n;
        }
    }
}

// ---------------- weight prep: transpose + bf16 hi/lo split ----------------
__global__ void k_prep(const float* __restrict__ Wl, const float* __restrict__ Wr) {
    int i = blockIdx.x * blockDim.x + threadIdx.x;
    if (i < 3 * 128 * 128) {
        int l = i >> 14, r = i & 16383, nn = r >> 7, kp = r & 127;
        int k = kp * 2;
        float v0, v1;
        if (k < 128) {
            v0 = Wl[l * 16384 + k * 128 + nn];
            v1 = Wl[l * 16384 + (k + 1) * 128 + nn];
        } else {
            v0 = Wr[l * 16384 + (k - 128) * 128 + nn];
            v1 = Wr[l * 16384 + (k - 127) * 128 + nn];
        }
        uint32_t hi, lo;
        split_pack(v0, v1, hi, lo);
        g_wth[i] = hi;
        g_wtl[i] = lo;
    }
}

// ---------------- mean aggregation: one warp per node, fp16 rows, 2-way unroll ----------------
__global__ void __launch_bounds__(256) k_agg(int n) {
    int w    = (blockIdx.x * blockDim.x + threadIdx.x) >> 5;
    int lane = threadIdx.x & 31;
    if (w >= n) return;
    int beg = g_off[w], end = g_off[w + 1];
    float4 acc0 = make_float4(0.f, 0.f, 0.f, 0.f);
    float4 acc1 = make_float4(0.f, 0.f, 0.f, 0.f);
    int e = beg;
    for (; e + 1 < end; e += 2) {
        int s0 = g_csr[e], s1 = g_csr[e + 1];
        uint2 u0 = g_xh[s0 * 32 + lane];
        uint2 u1 = g_xh[s1 * 32 + lane];
        float2 a = __half22float2(*(__half2*)&u0.x);
        float2 b = __half22float2(*(__half2*)&u0.y);
        float2 c = __half22float2(*(__half2*)&u1.x);
        float2 d = __half22float2(*(__half2*)&u1.y);
        acc0.x += a.x; acc0.y += a.y; acc0.z += b.x; acc0.w += b.y;
        acc1.x += c.x; acc1.y += c.y; acc1.z += d.x; acc1.w += d.y;
    }
    if (e < end) {
        int s = g_csr[e];
        uint2 u = g_xh[s * 32 + lane];
        float2 a = __half22float2(*(__half2*)&u.x);
        float2 b = __half22float2(*(__half2*)&u.y);
        acc0.x += a.x; acc0.y += a.y; acc0.z += b.x; acc0.w += b.y;
    }
    acc0.x += acc1.x; acc0.y += acc1.y; acc0.z += acc1.z; acc0.w += acc1.w;
    int cnt = end - beg;
    float inv = 1.f / (float)(cnt > 1 ? cnt : 1);
    acc0.x *= inv; acc0.y *= inv; acc0.z *= inv; acc0.w *= inv;
    *(float4*)&g_m[(size_t)w * H + lane * 4] = acc0;
}

// ---------------- mma.sync bf16-split GEMM ----------------
#define WST 72
#define PLANE (128 * WST)
#define GEMM_SMEM_MMA (4 * PLANE * 2 + 256 * 4 + 128 * 4)

__global__ void __launch_bounds__(256, 2) k_gemm_mma(const float* __restrict__ bl,
                                                     int layer, int n) {
    extern __shared__ char smraw[];
    __nv_bfloat16* Ah = (__nv_bfloat16*)smraw;
    __nv_bfloat16* Al = Ah + PLANE;
    __nv_bfloat16* Bh = Al + PLANE;
    __nv_bfloat16* Bl = Bh + PLANE;
    float* sred  = (float*)(Bl + PLANE);   // [256]
    float* sbias = sred + 256;             // [128]

    int t = threadIdx.x, lane = t & 31, wid = t >> 5;
    int gq = lane >> 2, tig = lane & 3;
    int rowBase = blockIdx.x * 128;
    int m0 = (wid >> 2) * 64, n0 = (wid & 3) * 32;
    const uint32_t* wth = g_wth + layer * 16384;
    const uint32_t* wtl = g_wtl + layer * 16384;

    if (t < 128) sbias[t] = bl[t];
    sred[t] = 0.f;

    float acc[4][4][4];
    #pragma unroll
    for (int mt = 0; mt < 4; mt++)
        #pragma unroll
        for (int nt = 0; nt < 4; nt++)
            #pragma unroll
            for (int q = 0; q < 4; q++) acc[mt][nt][q] = 0.f;

    for (int chunk = 0; chunk < 4; chunk++) {
        const float* Asrc = (chunk < 2) ? g_m : g_x;
        int k0 = (chunk & 1) * 64;
        __syncthreads();
        #pragma unroll
        for (int it = 0; it < 16; it++) {
            int f = t + it * 256;
            int row = f >> 5, kp = f & 31;
            float2 va = make_float2(0.f, 0.f);
            int grow = rowBase + row;
            if (grow < n) va = *(const float2*)&Asrc[(size_t)grow * 128 + k0 + kp * 2];
            uint32_t hi, lo;
            split_pack(va.x, va.y, hi, lo);
            *(uint32_t*)&Ah[row * WST + kp * 2] = hi;
            *(uint32_t*)&Al[row * WST + kp * 2] = lo;
            *(uint32_t*)&Bh[row * WST + kp * 2] = wth[row * 128 + chunk * 32 + kp];
            *(uint32_t*)&Bl[row * WST + kp * 2] = wtl[row * 128 + chunk * 32 + kp];
        }
        __syncthreads();

        #pragma unroll
        for (int ks = 0; ks < 4; ks++) {
            int kb = ks * 16;
            uint32_t bh[4][2], blo[4][2];
            #pragma unroll
            for (int nt = 0; nt < 4; nt++) {
                int brow = n0 + nt * 8 + gq;
                int kc = kb + tig * 2;
                bh[nt][0]  = *(const uint32_t*)&Bh[brow * WST + kc];
                bh[nt][1]  = *(const uint32_t*)&Bh[brow * WST + kc + 8];
                blo[nt][0] = *(const uint32_t*)&Bl[brow * WST + kc];
                blo[nt][1] = *(const uint32_t*)&Bl[brow * WST + kc + 8];
            }
            #pragma unroll
            for (int mt = 0; mt < 4; mt++) {
                int arow = m0 + mt * 16 + gq;
                int kc = kb + tig * 2;
                uint32_t ah[4], al[4];
                ah[0] = *(const uint32_t*)&Ah[arow * WST + kc];
                ah[1] = *(const uint32_t*)&Ah[(arow + 8) * WST + kc];
                ah[2] = *(const uint32_t*)&Ah[arow * WST + kc + 8];
                ah[3] = *(const uint32_t*)&Ah[(arow + 8) * WST + kc + 8];
                al[0] = *(const uint32_t*)&Al[arow * WST + kc];
                al[1] = *(const uint32_t*)&Al[(arow + 8) * WST + kc];
                al[2] = *(const uint32_t*)&Al[arow * WST + kc + 8];
                al[3] = *(const uint32_t*)&Al[(arow + 8) * WST + kc + 8];
                #pragma unroll
                for (int nt = 0; nt < 4; nt++) {
                    mma_bf16(acc[mt][nt], ah, bh[nt]);
                    mma_bf16(acc[mt][nt], ah, blo[nt]);
                    mma_bf16(acc[mt][nt], al, bh[nt]);
                }
            }
        }
    }

    float cs[4][2], cq[4][2];
    #pragma unroll
    for (int nt = 0; nt < 4; nt++) { cs[nt][0] = cs[nt][1] = cq[nt][0] = cq[nt][1] = 0.f; }
    #pragma unroll
    for (int mt = 0; mt < 4; mt++) {
        #pragma unroll
        for (int r = 0; r < 2; r++) {
            int row = rowBase + m0 + mt * 16 + gq + r * 8;
            if (row < n) {
                #pragma unroll
                for (int nt = 0; nt < 4; nt++) {
                    int col = n0 + nt * 8 + tig * 2;
                    float y0 = acc[mt][nt][r * 2 + 0] + sbias[col];
                    float y1 = acc[mt][nt][r * 2 + 1] + sbias[col + 1];
                    *(float2*)&g_y[(size_t)row * 128 + col] = make_float2(y0, y1);
                    cs[nt][0] += y0; cs[nt][1] += y1;
                    cq[nt][0] += y0 * y0; cq[nt][1] += y1 * y1;
                }
            }
        }
    }
    #pragma unroll
    for (int nt = 0; nt < 4; nt++) {
        #pragma unroll
        for (int j = 0; j < 2; j++) {
            float s = cs[nt][j], q = cq[nt][j];
            #pragma unroll
            for (int o = 4; o < 32; o <<= 1) {
                s += __shfl_xor_sync(0xffffffffu, s, o);
                q += __shfl_xor_sync(0xffffffffu, q, o);
            }
            if (gq == 0) {
                int col = n0 + nt * 8 + tig * 2 + j;
                atomicAdd(&sred[col], s);
                atomicAdd(&sred[128 + col], q);
            }
        }
    }
    __syncthreads();
    if (t < 128) {
        atomicAdd(&g_stats[t],       sred[t]);
        atomicAdd(&g_stats[128 + t], sred[128 + t]);
    }
}

__global__ void k_statfinal(const float* __restrict__ gamma, const float* __restrict__ beta, int n) {
    int c = threadIdx.x;
    float s = g_stats[c], s2 = g_stats[128 + c];
    float invn = 1.f / (float)n;
    float mu  = s * invn;
    float var = s2 * invn - mu * mu;
    float rs  = rsqrtf(var + 1e-5f);
    float sc  = rs * gamma[c];
    g_scale[c] = sc;
    g_shift[c] = beta[c] - mu * sc;
    g_stats[c] = 0.f;
    g_stats[128 + c] = 0.f;
}

// norm + relu, writes fp32 x and fp16 mirror
__global__ void k_norm(int n) {
    int i = blockIdx.x * blockDim.x + threadIdx.x;
    if (i < n * 32) {
        int q = i & 31;
        float4 y  = ((const float4*)g_y)[i];
        float4 sc = *(const float4*)&g_scale[q * 4];
        float4 sh = *(const float4*)&g_shift[q * 4];
        float4 r;
        r.x = fmaxf(y.x * sc.x + sh.x, 0.f);
        r.y = fmaxf(y.y * sc.y + sh.y, 0.f);
        r.z = fmaxf(y.z * sc.z + sh.z, 0.f);
        r.w = fmaxf(y.w * sc.w + sh.w, 0.f);
        ((float4*)g_x)[i] = r;
        g_xh[i] = f4_to_h4(r);
    }
}

// ---------------- attention scores ----------------
__global__ void __launch_bounds__(128) k_scores(const float* __restrict__ attn_W,
                                                const float* __restrict__ attn_b, int n) {
    __shared__ float Xs[32 * 132];
    __shared__ float Ws[128 * CL];
    __shared__ float bs[CL];
    int t = threadIdx.x;
    for (int i = t; i < 128 * CL; i += 128) Ws[i] = attn_W[i];
    if (t < CL) bs[t] = attn_b[t];
    int nb = blockIdx.x * 32;
    for (int i = t; i < 1024; i += 128) {
        int row = i >> 5, q = i & 31;
        float4 v = make_float4(0.f, 0.f, 0.f, 0.f);
        int node = nb + row;
        if (node < n) v = *(const float4*)&g_x[(size_t)node * H + q * 4];
        *(float4*)&Xs[row * 132 + q * 4] = v;
    }
    __syncthreads();
    int c = t & 15, ng = t >> 4;
    float a0 = bs[c], a1 = bs[c], a2 = bs[c], a3 = bs[c];
    const float* x0 = &Xs[(ng * 4 + 0) * 132];
    const float* x1 = &Xs[(ng * 4 + 1) * 132];
    const float* x2 = &Xs[(ng * 4 + 2) * 132];
    const float* x3 = &Xs[(ng * 4 + 3) * 132];
    #pragma unroll
    for (int k = 0; k < 128; k += 4) {
        float w0 = Ws[(k + 0) * CL + c], w1 = Ws[(k + 1) * CL + c];
        float w2 = Ws[(k + 2) * CL + c], w3 = Ws[(k + 3) * CL + c];
        float4 v;
        v = *(const float4*)&x0[k]; a0 += v.x * w0 + v.y * w1 + v.z * w2 + v.w * w3;
        v = *(const float4*)&x1[k]; a1 += v.x * w0 + v.y * w1 + v.z * w2 + v.w * w3;
        v = *(const float4*)&x2[k]; a2 += v.x * w0 + v.y * w1 + v.z * w2 + v.w * w3;
        v = *(const float4*)&x3[k]; a3 += v.x * w0 + v.y * w1 + v.z * w2 + v.w * w3;
    }
    int node = nb + ng * 4;
    if (node + 0 < n) g_scores[(size_t)(node + 0) * CL + c] = a0;
    if (node + 1 < n) g_scores[(size_t)(node + 1) * CL + c] = a1;
    if (node + 2 < n) g_scores[(size_t)(node + 2) * CL + c] = a2;
    if (node + 3 < n) g_scores[(size_t)(node + 3) * CL + c] = a3;
}

// ---------------- pooling: per-graph max + denom ----------------
__global__ void __launch_bounds__(256) k_poolmax() {
    int g = blockIdx.x, t = threadIdx.x, lane = t & 31, wid = t >> 5;
    int beg = g_goff[g], end = g_goff[g + 1];
    __shared__ float red[CL][9];
    __shared__ float smax[CL];
    float lv[CL];
    #pragma unroll
    for (int c = 0; c < CL; c++) lv[c] = -1e30f;
    for (int i = beg + t; i < end; i += 256) {
        const float4* sp = (const float4*)&g_scores[(size_t)i * CL];
        #pragma unroll
        for (int q = 0; q < 4; q++) {
            float4 s = sp[q];
            lv[4 * q + 0] = fmaxf(lv[4 * q + 0], s.x);
            lv[4 * q + 1] = fmaxf(lv[4 * q + 1], s.y);
            lv[4 * q + 2] = fmaxf(lv[4 * q + 2], s.z);
            lv[4 * q + 3] = fmaxf(lv[4 * q + 3], s.w);
        }
    }
    #pragma unroll
    for (int c = 0; c < CL; c++) {
        float v = lv[c];
        #pragma unroll
        for (int o = 16; o; o >>= 1) v = fmaxf(v, __shfl_xor_sync(0xffffffffu, v, o));
        if (lane == 0) red[c][wid] = v;
    }
    __syncthreads();
    if (t < CL) {
        float v = red[t][0];
        #pragma unroll
        for (int w = 1; w < 8; w++) v = fmaxf(v, red[t][w]);
        smax[t] = v;
    }
    __syncthreads();
    #pragma unroll
    for (int c = 0; c < CL; c++) lv[c] = 0.f;
    for (int i = beg + t; i < end; i += 256) {
        const float4* sp = (const float4*)&g_scores[(size_t)i * CL];
        #pragma unroll
        for (int q = 0; q < 4; q++) {
            float4 s = sp[q];
            lv[4 * q + 0] += expf(s.x - smax[4 * q + 0]);
            lv[4 * q + 1] += expf(s.y - smax[4 * q + 1]);
            lv[4 * q + 2] += expf(s.z - smax[4 * q + 2]);
            lv[4 * q + 3] += expf(s.w - smax[4 * q + 3]);
        }
    }
    #pragma unroll
    for (int c = 0; c < CL; c++) {
        float v = lv[c];
        #pragma unroll
        for (int o = 16; o; o >>= 1) v += __shfl_xor_sync(0xffffffffu, v, o);
        if (lane == 0) red[c][wid] = v;
    }
    __syncthreads();
    if (t < CL) {
        float v = 0.f;
        #pragma unroll
        for (int w = 0; w < 8; w++) v += red[t][w];
        g_pmax[g * CL + t] = smax[t];
        g_pinv[g * CL + t] = 1.f / v;
    }
}

// normalize weights in place: scores[i][c] = exp(s - max)*inv
__global__ void k_wcomp(const int* __restrict__ batch, int n) {
    int idx = blockIdx.x * blockDim.x + threadIdx.x;
    if (idx < n * CL) {
        int i = idx >> 4, c = idx & 15;
        int g = batch[i];
        float s = g_scores[idx];
        g_scores[idx] = expf(s - g_pmax[g * CL + c]) * g_pinv[g * CL + c];
    }
}

// weighted accumulate: grid (NG, 8 slices), atomics into g_clust
__global__ void __launch_bounds__(256) k_poolacc() {
    int g = blockIdx.x, slice = blockIdx.y;
    int beg = g_goff[g], end = g_goff[g + 1], len = end - beg;
    int s0 = beg + (int)(((long long)len * slice) >> 3);
    int s1 = beg + (int)(((long long)len * (slice + 1)) >> 3);
    int t = threadIdx.x;
    int c = t >> 4, h0 = (t & 15) * 8;
    float acc[8];
    #pragma unroll
    for (int j = 0; j < 8; j++) acc[j] = 0.f;
    for (int i = s0; i < s1; i++) {
        float w = g_scores[(size_t)i * CL + c];
        const float* xp = &g_x[(size_t)i * H + h0];
        float4 v0 = *(const float4*)xp;
        float4 v1 = *(const float4*)(xp + 4);
        acc[0] += w * v0.x; acc[1] += w * v0.y; acc[2] += w * v0.z; acc[3] += w * v0.w;
        acc[4] += w * v1.x; acc[5] += w * v1.y; acc[6] += w * v1.z; acc[7] += w * v1.w;
    }
    float* op = &g_clust[((size_t)g * CL + c) * H + h0];
    #pragma unroll
    for (int j = 0; j < 8; j++) atomicAdd(&op[j], acc[j]);
}

// ---------------- final projection ----------------
__global__ void __launch_bounds__(256) k_out(const float* __restrict__ W,
                                             const float* __restrict__ b,
                                             float* __restrict__ out) {
    int row  = blockIdx.x * 8 + (threadIdx.x >> 5);
    int lane = threadIdx.x & 31;
    if (row >= NG * CL) return;
    float4 acc = *(const float4*)&b[lane * 4];
    const float* cl = &g_clust[(size_t)row * H];
    #pragma unroll 4
    for (int k = 0; k < H; k++) {
        float c  = cl[k];
        float4 w = *(const float4*)&W[(size_t)k * ODIM + lane * 4];
        acc.x += c * w.x; acc.y += c * w.y; acc.z += c * w.z; acc.w += c * w.w;
    }
    *(float4*)&out[(size_t)row * ODIM + lane * 4] = acc;
}

// ---------------- launch ----------------
extern "C" void kernel_launch(void* const* d_in, const int* in_sizes, int n_in,
                              void* d_out, int out_size) {
    const float* emb    = (const float*)d_in[0];
    const float* Wl     = (const float*)d_in[1];
    const float* bl     = (const float*)d_in[2];
    const float* Wr     = (const float*)d_in[3];
    const float* gamma  = (const float*)d_in[4];
    const float* beta   = (const float*)d_in[5];
    const float* attn_W = (const float*)d_in[6];
    const float* attn_b = (const float*)d_in[7];
    const float* out_W  = (const float*)d_in[8];
    const float* out_b  = (const float*)d_in[9];
    const int* deg_idx  = (const int*)d_in[10];
    const int* edge     = (const int*)d_in[11];
    const int* batch    = (const int*)d_in[12];
    float* out          = (float*)d_out;

    const int n = NN, e = NE;

    cudaFuncSetAttribute(k_gemm_mma, cudaFuncAttributeMaxDynamicSharedMemorySize,
                         GEMM_SMEM_MMA);

    void* degp = nullptr;
    cudaGetSymbolAddress(&degp, g_deg);
    cudaMemsetAsync(degp, 0, NN * sizeof(int));
    void* clustp = nullptr;
    cudaGetSymbolAddress(&clustp, g_clust);
    cudaMemsetAsync(clustp, 0, NG * CL * H * sizeof(float));

    k_deg<<<(e + 255) / 256, 256>>>(edge + e, e);
    k_prep<<<(3 * 128 * 128 + 255) / 256, 256>>>(Wl, Wr);
    k_scan<<<1, 1024>>>(n);
    k_scatter<<<(e + 255) / 256, 256>>>(edge, edge + e, e);
    k_embed<<<(n * 32 + 255) / 256, 256>>>(emb, deg_idx, n);
    k_goff<<<(n + 255) / 256, 256>>>(batch, n);

    int gemmBlocks = (n + 127) / 128;
    for (int l = 0; l < 3; l++) {
        k_agg<<<(n * 32 + 255) / 256, 256>>>(n);
        k_gemm_mma<<<gemmBlocks, 256, GEMM_SMEM_MMA>>>(bl + l * H, l, n);
        k_statfinal<<<1, 128>>>(gamma + l * H, beta + l * H, n);
        k_norm<<<(n * 32 + 255) / 256, 256>>>(n);
    }

    k_scores<<<(n + 31) / 32, 128>>>(attn_W, attn_b, n);
    k_poolmax<<<NG, 256>>>();
    k_wcomp<<<(n * CL + 255) / 256, 256>>>(batch, n);
    dim3 pgrid(NG, 8);
    k_poolacc<<<pgrid, 256>>>();
    k_out<<<(NG * CL) / 8, 256>>>(out_W, out_b, out);
}

// round 6
// speedup vs baseline: 1.8695x; 1.0108x over previous
#include <cuda_runtime.h>
#include <cuda_bf16.h>
#include <cuda_fp16.h>
#include <cstdint>

#define NN 50000
#define NE 800000
#define NG 64
#define H  128
#define CL 16
#define ODIM 128

// ---------------- scratch (device globals; no allocation allowed) ----------------
__device__ uint2 g_xh[NN * 32];     // fp16 activations: 4 halves per uint2
__device__ uint2 g_mh[NN * 32];     // fp16 aggregated means
__device__ float g_y[NN * H];       // pre-norm GEMM output (fp32 for exact stats)
__device__ int   g_deg[NN];
__device__ int   g_off[NN + 1];
__device__ int   g_cur[NN];
__device__ int   g_csr[NE];
__device__ float g_scores[NN * CL];
__device__ int   g_goff[NG + 1];
__device__ float g_stats[3 * 256];  // per-layer sum/sumsq slots
__device__ float g_clust[NG * CL * H];
__device__ float g_pmax[NG * CL];
__device__ float g_pinv[NG * CL];
// weights pre-split into bf16 hi/lo, packed as u32 pairs along k:
// layout [layer][n][kpair]  (kpair = k/2, 128 pairs, k<128 -> Wl^T, k>=128 -> Wr^T)
__device__ uint32_t g_wth[3 * 128 * 128];
__device__ uint32_t g_wtl[3 * 128 * 128];

// ---------------- helpers ----------------
__device__ __forceinline__ void split_pack(float x, float y, uint32_t& hi, uint32_t& lo) {
    __nv_bfloat16 hx = __float2bfloat16(x);
    __nv_bfloat16 hy = __float2bfloat16(y);
    float rx = x - __bfloat162float(hx);
    float ry = y - __bfloat162float(hy);
    __nv_bfloat16 lx = __float2bfloat16(rx);
    __nv_bfloat16 ly = __float2bfloat16(ry);
    hi = ((uint32_t)__bfloat16_as_ushort(hy) << 16) | (uint32_t)__bfloat16_as_ushort(hx);
    lo = ((uint32_t)__bfloat16_as_ushort(ly) << 16) | (uint32_t)__bfloat16_as_ushort(lx);
}

__device__ __forceinline__ void mma_bf16(float* c, const uint32_t* a, const uint32_t* b) {
    asm volatile(
        "mma.sync.aligned.m16n8k16.row.col.f32.bf16.bf16.f32 "
        "{%0,%1,%2,%3}, {%4,%5,%6,%7}, {%8,%9}, {%0,%1,%2,%3};"
        : "+f"(c[0]), "+f"(c[1]), "+f"(c[2]), "+f"(c[3])
        : "r"(a[0]), "r"(a[1]), "r"(a[2]), "r"(a[3]), "r"(b[0]), "r"(b[1]));
}

__device__ __forceinline__ uint2 f4_to_h4(float4 v) {
    uint2 u;
    __half2 a = __floats2half2_rn(v.x, v.y);
    __half2 b = __floats2half2_rn(v.z, v.w);
    u.x = *(uint32_t*)&a;
    u.y = *(uint32_t*)&b;
    return u;
}
__device__ __forceinline__ float4 h4_to_f4(uint2 u) {
    float2 a = __half22float2(*(__half2*)&u.x);
    float2 b = __half22float2(*(__half2*)&u.y);
    return make_float4(a.x, a.y, b.x, b.y);
}

// ---------------- CSR build ----------------
__global__ void k_deg(const int* __restrict__ dst, int e) {
    int i = blockIdx.x * blockDim.x + threadIdx.x;
    if (i < e) atomicAdd(&g_deg[dst[i]], 1);
}

// single block, 1024 threads, 4 elems/thread: exclusive scan g_deg -> g_off, copy g_cur
__global__ void k_scan(int n) {
    __shared__ int wsum[32];
    __shared__ int carry;
    int t = threadIdx.x;
    if (t == 0) carry = 0;
    __syncthreads();
    for (int base = 0; base < n; base += 4096) {
        int i = base + t * 4;
        int4 v4 = make_int4(0, 0, 0, 0);
        if (i + 3 < n) v4 = *(const int4*)&g_deg[i];
        else {
            if (i + 0 < n) v4.x = g_deg[i + 0];
            if (i + 1 < n) v4.y = g_deg[i + 1];
            if (i + 2 < n) v4.z = g_deg[i + 2];
            if (i + 3 < n) v4.w = g_deg[i + 3];
        }
        int p1 = v4.x, p2 = p1 + v4.y, p3 = p2 + v4.z, v = p3 + v4.w;
        int x = v;
        #pragma unroll
        for (int d = 1; d < 32; d <<= 1) {
            int y = __shfl_up_sync(0xffffffffu, x, d);
            if ((t & 31) >= d) x += y;
        }
        if ((t & 31) == 31) wsum[t >> 5] = x;
        __syncthreads();
        if (t < 32) {
            int z = wsum[t];
            #pragma unroll
            for (int d = 1; d < 32; d <<= 1) {
                int y = __shfl_up_sync(0xffffffffu, z, d);
                if (t >= d) z += y;
            }
            wsum[t] = z;
        }
        __syncthreads();
        int incl = x + ((t >= 32) ? wsum[(t >> 5) - 1] : 0);
        int excl = incl - v + carry;
        int4 o = make_int4(excl, excl + p1, excl + p2, excl + p3);
        if (i + 3 < n) {
            *(int4*)&g_off[i] = o;
            *(int4*)&g_cur[i] = o;
        } else {
            if (i + 0 < n) { g_off[i + 0] = o.x; g_cur[i + 0] = o.x; }
            if (i + 1 < n) { g_off[i + 1] = o.y; g_cur[i + 1] = o.y; }
            if (i + 2 < n) { g_off[i + 2] = o.z; g_cur[i + 2] = o.z; }
            if (i + 3 < n) { g_off[i + 3] = o.w; g_cur[i + 3] = o.w; }
        }
        __syncthreads();
        if (t == 1023) carry += incl;
        __syncthreads();
    }
    if (t == 0) g_off[n] = carry;
}

__global__ void k_scatter(const int* __restrict__ src, const int* __restrict__ dst, int e) {
    int i = blockIdx.x * blockDim.x + threadIdx.x;
    if (i < e) {
        int d = dst[i];
        int p = atomicAdd(&g_cur[d], 1);
        g_csr[p] = src[i];
    }
}

// ---------------- embedding gather (fp16 only) ----------------
__global__ void k_embed(const float* __restrict__ emb, const int* __restrict__ degidx, int n) {
    int i = blockIdx.x * blockDim.x + threadIdx.x;
    if (i < n * 32) {
        int node = i >> 5, q = i & 31;
        int d = degidx[node];
        float4 v = ((const float4*)(emb + (size_t)d * H))[q];
        g_xh[i] = f4_to_h4(v);
    }
}

__global__ void k_goff(const int* __restrict__ batch, int n) {
    int i = blockIdx.x * blockDim.x + threadIdx.x;
    if (i < n) {
        int b  = batch[i];
        int bp = (i == 0) ? -1 : batch[i - 1];
        for (int g = bp + 1; g <= b; g++) g_goff[g] = i;
        if (i == n - 1) {
            for (int g = b + 1; g <= NG; g++) g_goff[g] = n;
        }
    }
}

// ---------------- weight prep: transpose + bf16 hi/lo split ----------------
__global__ void k_prep(const float* __restrict__ Wl, const float* __restrict__ Wr) {
    int i = blockIdx.x * blockDim.x + threadIdx.x;
    if (i < 3 * 128 * 128) {
        int l = i >> 14, r = i & 16383, nn = r >> 7, kp = r & 127;
        int k = kp * 2;
        float v0, v1;
        if (k < 128) {
            v0 = Wl[l * 16384 + k * 128 + nn];
            v1 = Wl[l * 16384 + (k + 1) * 128 + nn];
        } else {
            v0 = Wr[l * 16384 + (k - 128) * 128 + nn];
            v1 = Wr[l * 16384 + (k - 127) * 128 + nn];
        }
        uint32_t hi, lo;
        split_pack(v0, v1, hi, lo);
        g_wth[i] = hi;
        g_wtl[i] = lo;
    }
}

// ---------------- mean aggregation: one warp per node, fp16 in/out ----------------
__global__ void __launch_bounds__(256) k_agg(int n) {
    int w    = (blockIdx.x * blockDim.x + threadIdx.x) >> 5;
    int lane = threadIdx.x & 31;
    if (w >= n) return;
    int beg = g_off[w], end = g_off[w + 1];
    float4 acc0 = make_float4(0.f, 0.f, 0.f, 0.f);
    float4 acc1 = make_float4(0.f, 0.f, 0.f, 0.f);
    int e = beg;
    for (; e + 1 < end; e += 2) {
        int s0 = g_csr[e], s1 = g_csr[e + 1];
        float4 a = h4_to_f4(g_xh[s0 * 32 + lane]);
        float4 b = h4_to_f4(g_xh[s1 * 32 + lane]);
        acc0.x += a.x; acc0.y += a.y; acc0.z += a.z; acc0.w += a.w;
        acc1.x += b.x; acc1.y += b.y; acc1.z += b.z; acc1.w += b.w;
    }
    if (e < end) {
        float4 a = h4_to_f4(g_xh[g_csr[e] * 32 + lane]);
        acc0.x += a.x; acc0.y += a.y; acc0.z += a.z; acc0.w += a.w;
    }
    acc0.x += acc1.x; acc0.y += acc1.y; acc0.z += acc1.z; acc0.w += acc1.w;
    int cnt = end - beg;
    float inv = 1.f / (float)(cnt > 1 ? cnt : 1);
    acc0.x *= inv; acc0.y *= inv; acc0.z *= inv; acc0.w *= inv;
    g_mh[w * 32 + lane] = f4_to_h4(acc0);
}

// ---------------- mma.sync bf16-split GEMM (A from fp16 sources) ----------------
#define WST 72
#define PLANE (128 * WST)
#define GEMM_SMEM_MMA (4 * PLANE * 2 + 256 * 4 + 128 * 4)

__global__ void __launch_bounds__(256, 2) k_gemm_mma(const float* __restrict__ bl,
                                                     int layer, int n) {
    extern __shared__ char smraw[];
    __nv_bfloat16* Ah = (__nv_bfloat16*)smraw;
    __nv_bfloat16* Al = Ah + PLANE;
    __nv_bfloat16* Bh = Al + PLANE;
    __nv_bfloat16* Bl = Bh + PLANE;
    float* sred  = (float*)(Bl + PLANE);   // [256]
    float* sbias = sred + 256;             // [128]

    int t = threadIdx.x, lane = t & 31, wid = t >> 5;
    int gq = lane >> 2, tig = lane & 3;
    int rowBase = blockIdx.x * 128;
    int m0 = (wid >> 2) * 64, n0 = (wid & 3) * 32;
    const uint32_t* wth = g_wth + layer * 16384;
    const uint32_t* wtl = g_wtl + layer * 16384;

    if (t < 128) sbias[t] = bl[t];
    sred[t] = 0.f;

    float acc[4][4][4];
    #pragma unroll
    for (int mt = 0; mt < 4; mt++)
        #pragma unroll
        for (int nt = 0; nt < 4; nt++)
            #pragma unroll
            for (int q = 0; q < 4; q++) acc[mt][nt][q] = 0.f;

    for (int chunk = 0; chunk < 4; chunk++) {
        const uint2* Asrc = (chunk < 2) ? g_mh : g_xh;
        int qoff = (chunk & 1) * 16;
        __syncthreads();
        // stage 128 rows x 64 cols (16 quads) for A (fp16 -> bf16 split) and B
        #pragma unroll
        for (int it = 0; it < 8; it++) {
            int f = t + it * 256;            // 0..2047
            int row = f >> 4, qi = f & 15;
            int grow = rowBase + row;
            uint2 u = make_uint2(0u, 0u);
            if (grow < n) u = Asrc[grow * 32 + qoff + qi];
            float2 ab = __half22float2(*(__half2*)&u.x);
            float2 cd = __half22float2(*(__half2*)&u.y);
            uint32_t h0, l0, h1, l1;
            split_pack(ab.x, ab.y, h0, l0);
            split_pack(cd.x, cd.y, h1, l1);
            int kc = qi * 4;
            *(uint2*)&Ah[row * WST + kc] = make_uint2(h0, h1);
            *(uint2*)&Al[row * WST + kc] = make_uint2(l0, l1);
            *(uint2*)&Bh[row * WST + kc] = *(const uint2*)&wth[row * 128 + chunk * 32 + qi * 2];
            *(uint2*)&Bl[row * WST + kc] = *(const uint2*)&wtl[row * 128 + chunk * 32 + qi * 2];
        }
        __syncthreads();

        #pragma unroll
        for (int ks = 0; ks < 4; ks++) {
            int kb = ks * 16;
            uint32_t bh[4][2], blo[4][2];
            #pragma unroll
            for (int nt = 0; nt < 4; nt++) {
                int brow = n0 + nt * 8 + gq;
                int kc = kb + tig * 2;
                bh[nt][0]  = *(const uint32_t*)&Bh[brow * WST + kc];
                bh[nt][1]  = *(const uint32_t*)&Bh[brow * WST + kc + 8];
                blo[nt][0] = *(const uint32_t*)&Bl[brow * WST + kc];
                blo[nt][1] = *(const uint32_t*)&Bl[brow * WST + kc + 8];
            }
            #pragma unroll
            for (int mt = 0; mt < 4; mt++) {
                int arow = m0 + mt * 16 + gq;
                int kc = kb + tig * 2;
                uint32_t ah[4], al[4];
                ah[0] = *(const uint32_t*)&Ah[arow * WST + kc];
                ah[1] = *(const uint32_t*)&Ah[(arow + 8) * WST + kc];
                ah[2] = *(const uint32_t*)&Ah[arow * WST + kc + 8];
                ah[3] = *(const uint32_t*)&Ah[(arow + 8) * WST + kc + 8];
                al[0] = *(const uint32_t*)&Al[arow * WST + kc];
                al[1] = *(const uint32_t*)&Al[(arow + 8) * WST + kc];
                al[2] = *(const uint32_t*)&Al[arow * WST + kc + 8];
                al[3] = *(const uint32_t*)&Al[(arow + 8) * WST + kc + 8];
                #pragma unroll
                for (int nt = 0; nt < 4; nt++) {
                    mma_bf16(acc[mt][nt], ah, bh[nt]);
                    mma_bf16(acc[mt][nt], ah, blo[nt]);
                    mma_bf16(acc[mt][nt], al, bh[nt]);
                }
            }
        }
    }

    float cs[4][2], cq[4][2];
    #pragma unroll
    for (int nt = 0; nt < 4; nt++) { cs[nt][0] = cs[nt][1] = cq[nt][0] = cq[nt][1] = 0.f; }
    #pragma unroll
    for (int mt = 0; mt < 4; mt++) {
        #pragma unroll
        for (int r = 0; r < 2; r++) {
            int row = rowBase + m0 + mt * 16 + gq + r * 8;
            if (row < n) {
                #pragma unroll
                for (int nt = 0; nt < 4; nt++) {
                    int col = n0 + nt * 8 + tig * 2;
                    float y0 = acc[mt][nt][r * 2 + 0] + sbias[col];
                    float y1 = acc[mt][nt][r * 2 + 1] + sbias[col + 1];
                    *(float2*)&g_y[(size_t)row * 128 + col] = make_float2(y0, y1);
                    cs[nt][0] += y0; cs[nt][1] += y1;
                    cq[nt][0] += y0 * y0; cq[nt][1] += y1 * y1;
                }
            }
        }
    }
    #pragma unroll
    for (int nt = 0; nt < 4; nt++) {
        #pragma unroll
        for (int j = 0; j < 2; j++) {
            float s = cs[nt][j], q = cq[nt][j];
            #pragma unroll
            for (int o = 4; o < 32; o <<= 1) {
                s += __shfl_xor_sync(0xffffffffu, s, o);
                q += __shfl_xor_sync(0xffffffffu, q, o);
            }
            if (gq == 0) {
                int col = n0 + nt * 8 + tig * 2 + j;
                atomicAdd(&sred[col], s);
                atomicAdd(&sred[128 + col], q);
            }
        }
    }
    __syncthreads();
    if (t < 128) {
        atomicAdd(&g_stats[layer * 256 + t],       sred[t]);
        atomicAdd(&g_stats[layer * 256 + 128 + t], sred[128 + t]);
    }
}

// norm + relu from per-layer stats; writes fp16 mirror only
__global__ void k_norm(const float* __restrict__ gamma, const float* __restrict__ beta,
                       int layer, int n) {
    int i = blockIdx.x * blockDim.x + threadIdx.x;
    if (i < n * 32) {
        int q = i & 31;
        const float* st = g_stats + layer * 256;
        float invn = 1.f / (float)n;
        float4 y = ((const float4*)g_y)[i];
        float4 r;
        #pragma unroll
        for (int j = 0; j < 4; j++) {
            int c = q * 4 + j;
            float mu  = st[c] * invn;
            float var = st[128 + c] * invn - mu * mu;
            float sc  = rsqrtf(var + 1e-5f) * gamma[c];
            float sh  = beta[c] - mu * sc;
            float v = (&y.x)[j] * sc + sh;
            (&r.x)[j] = fmaxf(v, 0.f);
        }
        g_xh[i] = f4_to_h4(r);
    }
}

// ---------------- attention scores (fp16 input) ----------------
__global__ void __launch_bounds__(128) k_scores(const float* __restrict__ attn_W,
                                                const float* __restrict__ attn_b, int n) {
    __shared__ float Xs[32 * 132];
    __shared__ float Ws[128 * CL];
    __shared__ float bs[CL];
    int t = threadIdx.x;
    for (int i = t; i < 128 * CL; i += 128) Ws[i] = attn_W[i];
    if (t < CL) bs[t] = attn_b[t];
    int nb = blockIdx.x * 32;
    for (int i = t; i < 1024; i += 128) {
        int row = i >> 5, q = i & 31;
        float4 v = make_float4(0.f, 0.f, 0.f, 0.f);
        int node = nb + row;
        if (node < n) v = h4_to_f4(g_xh[node * 32 + q]);
        *(float4*)&Xs[row * 132 + q * 4] = v;
    }
    __syncthreads();
    int c = t & 15, ng = t >> 4;
    float a0 = bs[c], a1 = bs[c], a2 = bs[c], a3 = bs[c];
    const float* x0 = &Xs[(ng * 4 + 0) * 132];
    const float* x1 = &Xs[(ng * 4 + 1) * 132];
    const float* x2 = &Xs[(ng * 4 + 2) * 132];
    const float* x3 = &Xs[(ng * 4 + 3) * 132];
    #pragma unroll
    for (int k = 0; k < 128; k += 4) {
        float w0 = Ws[(k + 0) * CL + c], w1 = Ws[(k + 1) * CL + c];
        float w2 = Ws[(k + 2) * CL + c], w3 = Ws[(k + 3) * CL + c];
        float4 v;
        v = *(const float4*)&x0[k]; a0 += v.x * w0 + v.y * w1 + v.z * w2 + v.w * w3;
        v = *(const float4*)&x1[k]; a1 += v.x * w0 + v.y * w1 + v.z * w2 + v.w * w3;
        v = *(const float4*)&x2[k]; a2 += v.x * w0 + v.y * w1 + v.z * w2 + v.w * w3;
        v = *(const float4*)&x3[k]; a3 += v.x * w0 + v.y * w1 + v.z * w2 + v.w * w3;
    }
    int node = nb + ng * 4;
    if (node + 0 < n) g_scores[(size_t)(node + 0) * CL + c] = a0;
    if (node + 1 < n) g_scores[(size_t)(node + 1) * CL + c] = a1;
    if (node + 2 < n) g_scores[(size_t)(node + 2) * CL + c] = a2;
    if (node + 3 < n) g_scores[(size_t)(node + 3) * CL + c] = a3;
}

// ---------------- pooling: per-graph max + denom ----------------
__global__ void __launch_bounds__(256) k_poolmax() {
    int g = blockIdx.x, t = threadIdx.x, lane = t & 31, wid = t >> 5;
    int beg = g_goff[g], end = g_goff[g + 1];
    __shared__ float red[CL][9];
    __shared__ float smax[CL];
    float lv[CL];
    #pragma unroll
    for (int c = 0; c < CL; c++) lv[c] = -1e30f;
    for (int i = beg + t; i < end; i += 256) {
        const float4* sp = (const float4*)&g_scores[(size_t)i * CL];
        #pragma unroll
        for (int q = 0; q < 4; q++) {
            float4 s = sp[q];
            lv[4 * q + 0] = fmaxf(lv[4 * q + 0], s.x);
            lv[4 * q + 1] = fmaxf(lv[4 * q + 1], s.y);
            lv[4 * q + 2] = fmaxf(lv[4 * q + 2], s.z);
            lv[4 * q + 3] = fmaxf(lv[4 * q + 3], s.w);
        }
    }
    #pragma unroll
    for (int c = 0; c < CL; c++) {
        float v = lv[c];
        #pragma unroll
        for (int o = 16; o; o >>= 1) v = fmaxf(v, __shfl_xor_sync(0xffffffffu, v, o));
        if (lane == 0) red[c][wid] = v;
    }
    __syncthreads();
    if (t < CL) {
        float v = red[t][0];
        #pragma unroll
        for (int w = 1; w < 8; w++) v = fmaxf(v, red[t][w]);
        smax[t] = v;
    }
    __syncthreads();
    #pragma unroll
    for (int c = 0; c < CL; c++) lv[c] = 0.f;
    for (int i = beg + t; i < end; i += 256) {
        const float4* sp = (const float4*)&g_scores[(size_t)i * CL];
        #pragma unroll
        for (int q = 0; q < 4; q++) {
            float4 s = sp[q];
            lv[4 * q + 0] += expf(s.x - smax[4 * q + 0]);
            lv[4 * q + 1] += expf(s.y - smax[4 * q + 1]);
            lv[4 * q + 2] += expf(s.z - smax[4 * q + 2]);
            lv[4 * q + 3] += expf(s.w - smax[4 * q + 3]);
        }
    }
    #pragma unroll
    for (int c = 0; c < CL; c++) {
        float v = lv[c];
        #pragma unroll
        for (int o = 16; o; o >>= 1) v += __shfl_xor_sync(0xffffffffu, v, o);
        if (lane == 0) red[c][wid] = v;
    }
    __syncthreads();
    if (t < CL) {
        float v = 0.f;
        #pragma unroll
        for (int w = 0; w < 8; w++) v += red[t][w];
        g_pmax[g * CL + t] = smax[t];
        g_pinv[g * CL + t] = 1.f / v;
    }
}

// weighted accumulate (softmax weight computed inline): grid (NG, 8 slices)
__global__ void __launch_bounds__(256) k_poolacc() {
    int g = blockIdx.x, slice = blockIdx.y;
    int beg = g_goff[g], end = g_goff[g + 1], len = end - beg;
    int s0 = beg + (int)(((long long)len * slice) >> 3);
    int s1 = beg + (int)(((long long)len * (slice + 1)) >> 3);
    int t = threadIdx.x;
    int c = t >> 4, h0 = (t & 15) * 8;
    int qb = h0 >> 2;
    float mx = g_pmax[g * CL + c], iv = g_pinv[g * CL + c];
    float acc[8];
    #pragma unroll
    for (int j = 0; j < 8; j++) acc[j] = 0.f;
    for (int i = s0; i < s1; i++) {
        float w = expf(g_scores[(size_t)i * CL + c] - mx) * iv;
        float4 v0 = h4_to_f4(g_xh[i * 32 + qb]);
        float4 v1 = h4_to_f4(g_xh[i * 32 + qb + 1]);
        acc[0] += w * v0.x; acc[1] += w * v0.y; acc[2] += w * v0.z; acc[3] += w * v0.w;
        acc[4] += w * v1.x; acc[5] += w * v1.y; acc[6] += w * v1.z; acc[7] += w * v1.w;
    }
    float* op = &g_clust[((size_t)g * CL + c) * H + h0];
    #pragma unroll
    for (int j = 0; j < 8; j++) atomicAdd(&op[j], acc[j]);
}

// ---------------- final projection ----------------
__global__ void __launch_bounds__(256) k_out(const float* __restrict__ W,
                                             const float* __restrict__ b,
                                             float* __restrict__ out) {
    int row  = blockIdx.x * 8 + (threadIdx.x >> 5);
    int lane = threadIdx.x & 31;
    if (row >= NG * CL) return;
    float4 acc = *(const float4*)&b[lane * 4];
    const float* cl = &g_clust[(size_t)row * H];
    #pragma unroll 4
    for (int k = 0; k < H; k++) {
        float c  = cl[k];
        float4 w = *(const float4*)&W[(size_t)k * ODIM + lane * 4];
        acc.x += c * w.x; acc.y += c * w.y; acc.z += c * w.z; acc.w += c * w.w;
    }
    *(float4*)&out[(size_t)row * ODIM + lane * 4] = acc;
}

// ---------------- launch ----------------
extern "C" void kernel_launch(void* const* d_in, const int* in_sizes, int n_in,
                              void* d_out, int out_size) {
    const float* emb    = (const float*)d_in[0];
    const float* Wl     = (const float*)d_in[1];
    const float* bl     = (const float*)d_in[2];
    const float* Wr     = (const float*)d_in[3];
    const float* gamma  = (const float*)d_in[4];
    const float* beta   = (const float*)d_in[5];
    const float* attn_W = (const float*)d_in[6];
    const float* attn_b = (const float*)d_in[7];
    const float* out_W  = (const float*)d_in[8];
    const float* out_b  = (const float*)d_in[9];
    const int* deg_idx  = (const int*)d_in[10];
    const int* edge     = (const int*)d_in[11];
    const int* batch    = (const int*)d_in[12];
    float* out          = (float*)d_out;

    const int n = NN, e = NE;

    cudaFuncSetAttribute(k_gemm_mma, cudaFuncAttributeMaxDynamicSharedMemorySize,
                         GEMM_SMEM_MMA);

    void* p = nullptr;
    cudaGetSymbolAddress(&p, g_deg);
    cudaMemsetAsync(p, 0, NN * sizeof(int));
    cudaGetSymbolAddress(&p, g_clust);
    cudaMemsetAsync(p, 0, NG * CL * H * sizeof(float));
    cudaGetSymbolAddress(&p, g_stats);
    cudaMemsetAsync(p, 0, 3 * 256 * sizeof(float));

    k_deg<<<(e + 255) / 256, 256>>>(edge + e, e);
    k_prep<<<(3 * 128 * 128 + 255) / 256, 256>>>(Wl, Wr);
    k_scan<<<1, 1024>>>(n);
    k_scatter<<<(e + 255) / 256, 256>>>(edge, edge + e, e);
    k_embed<<<(n * 32 + 255) / 256, 256>>>(emb, deg_idx, n);
    k_goff<<<(n + 255) / 256, 256>>>(batch, n);

    int gemmBlocks = (n + 127) / 128;
    for (int l = 0; l < 3; l++) {
        k_agg<<<(n * 32 + 255) / 256, 256>>>(n);
        k_gemm_mma<<<gemmBlocks, 256, GEMM_SMEM_MMA>>>(bl + l * H, l, n);
        k_norm<<<(n * 32 + 255) / 256, 256>>>(gamma + l * H, beta + l * H, l, n);
    }

    k_scores<<<(n + 31) / 32, 128>>>(attn_W, attn_b, n);
    k_poolmax<<<NG, 256>>>();
    dim3 pgrid(NG, 8);
    k_poolacc<<<pgrid, 256>>>();
    k_out<<<(NG * CL) / 8, 256>>>(out_W, out_b, out);
}